// round 1
// baseline (speedup 1.0000x reference)
#include <cuda_runtime.h>
#include <cuda_bf16.h>
#include <cstdint>

#define NN   50000
#define EE   800000
#define HH   4
#define CC   64
#define DIN  128
#define D1   256

// ---------------- device scratch (no allocations allowed) ----------------
__device__ float g_xs[NN * D1];        // xs = X @ Wsrc for current layer
__device__ float g_acc[NN * D1];       // layer-1 accumulator (skip + messages)
__device__ float g_h[NN * D1];         // hidden after LN+ReLU
__device__ float g_asad[NN * 8];       // per node: a_s[0..3], a_d[0..3]
__device__ float g_alpha[EE * HH];     // per CSR position: e / ex / alpha (in-place)
__device__ float g_vcat[D1 * 8];       // folded att vectors: vcat[k][j], j<4 src, j>=4 dst
__device__ int   g_deg[NN];
__device__ int   g_rowptr[NN + 1];
__device__ int   g_cursor[NN];
__device__ int   g_csr[EE];

// ---------------- CSR build ----------------
__global__ void k_zero_deg() {
    int t = blockIdx.x * blockDim.x + threadIdx.x;
    if (t < NN) g_deg[t] = 0;
}

__global__ void k_count(const int* __restrict__ dst) {
    int t = blockIdx.x * blockDim.x + threadIdx.x;
    if (t < EE) atomicAdd(&g_deg[dst[t]], 1);
}

__global__ void k_scan() {
    __shared__ int sums[1024];
    int t = threadIdx.x;
    const int CH = (NN + 1023) / 1024;
    int base = t * CH;
    int s = 0;
    for (int i = 0; i < CH; i++) {
        int idx = base + i;
        if (idx < NN) s += g_deg[idx];
    }
    int my = s;
    sums[t] = s;
    __syncthreads();
    for (int d = 1; d < 1024; d <<= 1) {
        int v = (t >= d) ? sums[t - d] : 0;
        __syncthreads();
        sums[t] += v;
        __syncthreads();
    }
    if (t == 1023) g_rowptr[NN] = sums[1023];
    int off = sums[t] - my;  // exclusive
    for (int i = 0; i < CH; i++) {
        int idx = base + i;
        if (idx < NN) {
            g_rowptr[idx] = off;
            g_cursor[idx] = off;
            off += g_deg[idx];
        }
    }
}

__global__ void k_fill(const int* __restrict__ dst) {
    int t = blockIdx.x * blockDim.x + threadIdx.x;
    if (t < EE) {
        int d = dst[t];
        int p = atomicAdd(&g_cursor[d], 1);
        g_csr[p] = t;
    }
}

// ---------------- fold att vectors: vcat[k][h] = sum_c W[k][h*C+c]*att[h][c] ----------------
__global__ void k_vcat(const float* __restrict__ Wsrc, const float* __restrict__ Wdst,
                       const float* __restrict__ atts, const float* __restrict__ attd, int K) {
    int t = blockIdx.x * blockDim.x + threadIdx.x;
    if (t >= K * 8) return;
    int k = t >> 3, j = t & 7;
    const float* W   = (j < 4) ? Wsrc : Wdst;
    const float* att = (j < 4) ? atts : attd;
    int h = j & 3;
    float s = 0.f;
    for (int c = 0; c < CC; c++) s = fmaf(W[k * D1 + h * CC + c], att[h * CC + c], s);
    g_vcat[t] = s;
}

// ---------------- tiled fp32 GEMM: Y[N][256] = X[N][K] @ W[K][256] (+bias1+bias2) ----------------
template <int K>
__global__ void __launch_bounds__(256)
k_gemm(const float* __restrict__ X, const float* __restrict__ W,
       const float* __restrict__ bias1, const float* __restrict__ bias2,
       float* __restrict__ Y) {
    // BM=128, BN=64, BK=16, 256 threads, 8x4 micro-tile
    __shared__ float Xs[16][128 + 4];
    __shared__ float Ws[16][64];
    const int tid = threadIdx.x;
    const int bm = blockIdx.x * 128, bn = blockIdx.y * 64;
    const int ty = tid >> 4, tx = tid & 15;
    float acc[8][4] = {};

    for (int k0 = 0; k0 < K; k0 += 16) {
        // load X tile (transposed into smem)
#pragma unroll
        for (int i = 0; i < 2; i++) {
            int f = tid + i * 256;           // 512 float4 loads
            int row = f >> 2, kq = f & 3;
            int gr = bm + row;
            float4 v = make_float4(0.f, 0.f, 0.f, 0.f);
            if (gr < NN) v = *(const float4*)(X + (size_t)gr * K + k0 + kq * 4);
            Xs[kq * 4 + 0][row] = v.x;
            Xs[kq * 4 + 1][row] = v.y;
            Xs[kq * 4 + 2][row] = v.z;
            Xs[kq * 4 + 3][row] = v.w;
        }
        // load W tile
        {
            int row = tid >> 4, cq = tid & 15;  // 16x16 float4
            float4 v = *(const float4*)(W + (size_t)(k0 + row) * D1 + bn + cq * 4);
            *(float4*)&Ws[row][cq * 4] = v;
        }
        __syncthreads();
#pragma unroll
        for (int k = 0; k < 16; k++) {
            float4 a0 = *(const float4*)&Xs[k][ty * 8];
            float4 a1 = *(const float4*)&Xs[k][ty * 8 + 4];
            float4 bv = *(const float4*)&Ws[k][tx * 4];
            float a[8] = {a0.x, a0.y, a0.z, a0.w, a1.x, a1.y, a1.z, a1.w};
            float b[4] = {bv.x, bv.y, bv.z, bv.w};
#pragma unroll
            for (int i = 0; i < 8; i++)
#pragma unroll
                for (int j = 0; j < 4; j++) acc[i][j] = fmaf(a[i], b[j], acc[i][j]);
        }
        __syncthreads();
    }

    int gc = bn + tx * 4;
    float bb[4] = {0.f, 0.f, 0.f, 0.f};
    if (bias1) {
#pragma unroll
        for (int j = 0; j < 4; j++) bb[j] += bias1[gc + j];
    }
    if (bias2) {
#pragma unroll
        for (int j = 0; j < 4; j++) bb[j] += bias2[gc + j];
    }
#pragma unroll
    for (int i = 0; i < 8; i++) {
        int gr = bm + ty * 8 + i;
        if (gr < NN) {
            float4 o = make_float4(acc[i][0] + bb[0], acc[i][1] + bb[1],
                                   acc[i][2] + bb[2], acc[i][3] + bb[3]);
            *(float4*)(Y + (size_t)gr * D1 + gc) = o;
        }
    }
}

// ---------------- per-node attention pre-scores: a_s, a_d = X @ vcat ----------------
template <int K>
__global__ void k_asad(const float* __restrict__ X) {
    int t = blockIdx.x * blockDim.x + threadIdx.x;
    if (t >= NN * 8) return;
    int n = t >> 3, j = t & 7;
    const float* xr = X + (size_t)n * K;
    float s = 0.f;
    for (int k = 0; k < K; k++) s = fmaf(xr[k], g_vcat[k * 8 + j], s);
    g_asad[t] = s;
}

// ---------------- segmented softmax over in-edges (thread per (node,head)) ----------------
__global__ void k_softmax(const int* __restrict__ src) {
    int t = blockIdx.x * blockDim.x + threadIdx.x;
    if (t >= NN * HH) return;
    int n = t >> 2, h = t & 3;
    int rs = g_rowptr[n], re = g_rowptr[n + 1];
    if (rs == re) return;
    float ad = g_asad[n * 8 + 4 + h];
    float mx = -1e30f;
    for (int p = rs; p < re; p++) {
        int eid = g_csr[p];
        int s = src[eid];
        float a = g_asad[s * 8 + h] + ad;
        a = (a > 0.f) ? a : 0.2f * a;  // leaky_relu 0.2
        g_alpha[(size_t)p * 4 + h] = a;
        mx = fmaxf(mx, a);
    }
    float den = 0.f;
    for (int p = rs; p < re; p++) {
        float ex = __expf(g_alpha[(size_t)p * 4 + h] - mx);
        g_alpha[(size_t)p * 4 + h] = ex;
        den += ex;
    }
    float inv = 1.f / (den + 1e-16f);
    for (int p = rs; p < re; p++) g_alpha[(size_t)p * 4 + h] *= inv;
}

// ---------------- message aggregation: warp per node, accumulate alpha * xs[src] ----------------
__global__ void k_aggregate(const float* __restrict__ xs, float* __restrict__ acc_out,
                            const int* __restrict__ src) {
    int w = (blockIdx.x * blockDim.x + threadIdx.x) >> 5;
    int l = threadIdx.x & 31;
    if (w >= NN) return;
    int rs = g_rowptr[w], re = g_rowptr[w + 1];
    if (rs == re) return;
    float acc[8] = {0.f, 0.f, 0.f, 0.f, 0.f, 0.f, 0.f, 0.f};
    for (int p = rs; p < re; p++) {
        int eid = g_csr[p];
        int s = src[eid];
        float4 al = *(const float4*)(g_alpha + (size_t)p * 4);
        const float* xr = xs + (size_t)s * D1;
        float a4[4] = {al.x, al.y, al.z, al.w};
#pragma unroll
        for (int k = 0; k < 8; k++) acc[k] = fmaf(a4[k >> 1], xr[l + 32 * k], acc[k]);
    }
    float* o = acc_out + (size_t)w * D1;
#pragma unroll
    for (int k = 0; k < 8; k++) o[l + 32 * k] += acc[k];
}

// ---------------- LayerNorm + ReLU (warp per node) ----------------
__global__ void k_lnrelu(const float* __restrict__ in, float* __restrict__ out,
                         const float* __restrict__ gamma, const float* __restrict__ beta) {
    int w = (blockIdx.x * blockDim.x + threadIdx.x) >> 5;
    int l = threadIdx.x & 31;
    if (w >= NN) return;
    const float* r = in + (size_t)w * D1;
    float v[8];
    float s = 0.f, sq = 0.f;
#pragma unroll
    for (int k = 0; k < 8; k++) {
        v[k] = r[l + 32 * k];
        s += v[k];
        sq += v[k] * v[k];
    }
#pragma unroll
    for (int d = 16; d > 0; d >>= 1) {
        s += __shfl_xor_sync(0xFFFFFFFFu, s, d);
        sq += __shfl_xor_sync(0xFFFFFFFFu, sq, d);
    }
    float mean = s * (1.f / D1);
    float var = sq * (1.f / D1) - mean * mean;
    float inv = rsqrtf(var + 1e-5f);
    float* o = out + (size_t)w * D1;
#pragma unroll
    for (int k = 0; k < 8; k++) {
        int c = l + 32 * k;
        float t = (v[k] - mean) * inv * gamma[c] + beta[c];
        o[c] = fmaxf(t, 0.f);
    }
}

// ---------------- host launch ----------------
extern "C" void kernel_launch(void* const* d_in, const int* in_sizes, int n_in,
                              void* d_out, int out_size) {
    const float* x     = (const float*)d_in[0];
    const int*   ei    = (const int*)d_in[1];
    const float* Wsrc1 = (const float*)d_in[2];
    const float* Wdst1 = (const float*)d_in[3];
    const float* atts1 = (const float*)d_in[4];
    const float* attd1 = (const float*)d_in[5];
    const float* b1    = (const float*)d_in[6];
    const float* Wlin1 = (const float*)d_in[7];
    const float* blin1 = (const float*)d_in[8];
    const float* gamma = (const float*)d_in[9];
    const float* beta  = (const float*)d_in[10];
    const float* Wsrc2 = (const float*)d_in[11];
    const float* Wdst2 = (const float*)d_in[12];
    const float* atts2 = (const float*)d_in[13];
    const float* attd2 = (const float*)d_in[14];
    const float* b2    = (const float*)d_in[15];
    const float* Wlin2 = (const float*)d_in[16];
    const float* blin2 = (const float*)d_in[17];
    float* out = (float*)d_out;

    const int* src = ei;
    const int* dst = ei + EE;

    float *xs_p, *acc_p, *h_p;
    cudaGetSymbolAddress((void**)&xs_p, g_xs);
    cudaGetSymbolAddress((void**)&acc_p, g_acc);
    cudaGetSymbolAddress((void**)&h_p, g_h);

    // CSR (graph is identical for both layers)
    k_zero_deg<<<(NN + 255) / 256, 256>>>();
    k_count<<<(EE + 255) / 256, 256>>>(dst);
    k_scan<<<1, 1024>>>();
    k_fill<<<(EE + 255) / 256, 256>>>(dst);

    dim3 gg((NN + 127) / 128, D1 / 64);

    // ---- layer 1 (K = DIN = 128) ----
    k_vcat<<<(DIN * 8 + 255) / 256, 256>>>(Wsrc1, Wdst1, atts1, attd1, DIN);
    k_gemm<DIN><<<gg, 256>>>(x, Wsrc1, nullptr, nullptr, xs_p);
    k_gemm<DIN><<<gg, 256>>>(x, Wlin1, blin1, b1, acc_p);  // skip + both biases
    k_asad<DIN><<<(NN * 8 + 255) / 256, 256>>>(x);
    k_softmax<<<(NN * HH + 255) / 256, 256>>>(src);
    k_aggregate<<<(NN + 7) / 8, 256>>>(xs_p, acc_p, src);
    k_lnrelu<<<(NN + 7) / 8, 256>>>(acc_p, h_p, gamma, beta);

    // ---- layer 2 (K = D1 = 256), output accumulates directly into d_out ----
    k_vcat<<<(D1 * 8 + 255) / 256, 256>>>(Wsrc2, Wdst2, atts2, attd2, D1);
    k_gemm<D1><<<gg, 256>>>(h_p, Wsrc2, nullptr, nullptr, xs_p);
    k_gemm<D1><<<gg, 256>>>(h_p, Wlin2, blin2, b2, out);
    k_asad<D1><<<(NN * 8 + 255) / 256, 256>>>(h_p);
    k_softmax<<<(NN * HH + 255) / 256, 256>>>(src);
    k_aggregate<<<(NN + 7) / 8, 256>>>(xs_p, out, src);
}

// round 3
// speedup vs baseline: 1.4397x; 1.4397x over previous
#include <cuda_runtime.h>
#include <cuda_bf16.h>
#include <cstdint>

#define NN   50000
#define EE   800000
#define HH   4
#define CC   64
#define DIN  128
#define D1   256

// ---------------- device scratch ----------------
__device__ float g_xs[NN * D1];
__device__ float g_acc[NN * D1];
__device__ float g_h[NN * D1];
__device__ float g_asad[NN * 8];       // per node: a_s[0..3], a_d[0..3]
__device__ float g_alpha[EE * HH];     // CSR-ordered
__device__ float g_vcat[D1 * 8];
__device__ int   g_deg[NN];
__device__ int   g_rowptr[NN + 1];
__device__ int   g_cursor[NN];
__device__ int   g_csr[EE];

// ---------------- CSR build ----------------
__global__ void k_zero_deg() {
    int t = blockIdx.x * blockDim.x + threadIdx.x;
    if (t < NN) g_deg[t] = 0;
}

__global__ void k_count(const int* __restrict__ dst) {
    int t = blockIdx.x * blockDim.x + threadIdx.x;
    if (t < EE) atomicAdd(&g_deg[dst[t]], 1);
}

__global__ void k_scan() {
    __shared__ int sums[1024];
    int t = threadIdx.x;
    const int CH = (NN + 1023) / 1024;
    int base = t * CH;
    int s = 0;
    for (int i = 0; i < CH; i++) {
        int idx = base + i;
        if (idx < NN) s += g_deg[idx];
    }
    int my = s;
    sums[t] = s;
    __syncthreads();
    for (int d = 1; d < 1024; d <<= 1) {
        int v = (t >= d) ? sums[t - d] : 0;
        __syncthreads();
        sums[t] += v;
        __syncthreads();
    }
    if (t == 1023) g_rowptr[NN] = sums[1023];
    int off = sums[t] - my;
    for (int i = 0; i < CH; i++) {
        int idx = base + i;
        if (idx < NN) {
            g_rowptr[idx] = off;
            g_cursor[idx] = off;
            off += g_deg[idx];
        }
    }
}

__global__ void k_fill(const int* __restrict__ dst) {
    int t = blockIdx.x * blockDim.x + threadIdx.x;
    if (t < EE) {
        int d = dst[t];
        int p = atomicAdd(&g_cursor[d], 1);
        g_csr[p] = t;
    }
}

// ---------------- fold att vectors ----------------
__global__ void k_vcat(const float* __restrict__ Wsrc, const float* __restrict__ Wdst,
                       const float* __restrict__ atts, const float* __restrict__ attd, int K) {
    int t = blockIdx.x * blockDim.x + threadIdx.x;
    if (t >= K * 8) return;
    int k = t >> 3, j = t & 7;
    const float* W   = (j < 4) ? Wsrc : Wdst;
    const float* att = (j < 4) ? atts : attd;
    int h = j & 3;
    float s = 0.f;
    for (int c = 0; c < CC; c++) s = fmaf(W[k * D1 + h * CC + c], att[h * CC + c], s);
    g_vcat[t] = s;
}

// ---------------- TF32 tensor-core GEMM: Y[N][256] = X[N][K] @ W[K][256] ----------------
__device__ __forceinline__ float to_tf32(float x) {
    uint32_t y;
    asm("cvt.rna.tf32.f32 %0, %1;" : "=r"(y) : "f"(x));
    return __uint_as_float(y);
}

__device__ __forceinline__ void mma_tf32(float* d, const uint32_t* a, const uint32_t* b) {
    asm volatile(
        "mma.sync.aligned.m16n8k8.row.col.f32.tf32.tf32.f32 "
        "{%0,%1,%2,%3}, {%4,%5,%6,%7}, {%8,%9}, {%0,%1,%2,%3};"
        : "+f"(d[0]), "+f"(d[1]), "+f"(d[2]), "+f"(d[3])
        : "r"(a[0]), "r"(a[1]), "r"(a[2]), "r"(a[3]), "r"(b[0]), "r"(b[1]));
}

template <int K>
__global__ void __launch_bounds__(256)
k_gemm(const float* __restrict__ X, const float* __restrict__ W,
       const float* __restrict__ bias1, const float* __restrict__ bias2,
       float* __restrict__ Y) {
    // BM=128, BN=64, BK=32; 8 warps in 4(m)x2(n); warp tile 32x32; mma m16n8k8
    __shared__ float As[128][36];   // [m][k], pad 4
    __shared__ float Ws[32][68];    // [k][n], pad 4

    const int tid = threadIdx.x;
    const int bm = blockIdx.x * 128, bn = blockIdx.y * 64;
    const int lane = tid & 31, wid = tid >> 5;
    const int wm = wid >> 1, wn = wid & 1;
    const int gid = lane >> 2, tig = lane & 3;

    float acc[2][4][4];
#pragma unroll
    for (int i = 0; i < 2; i++)
#pragma unroll
        for (int j = 0; j < 4; j++)
#pragma unroll
            for (int q = 0; q < 4; q++) acc[i][j][q] = 0.f;

    for (int k0 = 0; k0 < K; k0 += 32) {
        // A tile: 128 rows x 32 floats = 1024 float4
#pragma unroll
        for (int i = 0; i < 4; i++) {
            int f = tid + i * 256;
            int row = f >> 3, seg = f & 7;
            int gr = bm + row;
            float4 v = make_float4(0.f, 0.f, 0.f, 0.f);
            if (gr < NN) v = *(const float4*)(X + (size_t)gr * K + k0 + seg * 4);
            v.x = to_tf32(v.x); v.y = to_tf32(v.y); v.z = to_tf32(v.z); v.w = to_tf32(v.w);
            *(float4*)&As[row][seg * 4] = v;
        }
        // W tile: 32 rows x 64 floats = 512 float4
#pragma unroll
        for (int i = 0; i < 2; i++) {
            int f = tid + i * 256;
            int row = f >> 4, seg = f & 15;
            float4 v = *(const float4*)(W + (size_t)(k0 + row) * D1 + bn + seg * 4);
            v.x = to_tf32(v.x); v.y = to_tf32(v.y); v.z = to_tf32(v.z); v.w = to_tf32(v.w);
            *(float4*)&Ws[row][seg * 4] = v;
        }
        __syncthreads();

#pragma unroll
        for (int ks = 0; ks < 32; ks += 8) {
            uint32_t a[2][4], b[4][2];
#pragma unroll
            for (int mt = 0; mt < 2; mt++) {
                int mr = wm * 32 + mt * 16 + gid;
                a[mt][0] = __float_as_uint(As[mr][ks + tig]);
                a[mt][1] = __float_as_uint(As[mr + 8][ks + tig]);
                a[mt][2] = __float_as_uint(As[mr][ks + tig + 4]);
                a[mt][3] = __float_as_uint(As[mr + 8][ks + tig + 4]);
            }
#pragma unroll
            for (int nt = 0; nt < 4; nt++) {
                int nc = wn * 32 + nt * 8 + gid;
                b[nt][0] = __float_as_uint(Ws[ks + tig][nc]);
                b[nt][1] = __float_as_uint(Ws[ks + tig + 4][nc]);
            }
#pragma unroll
            for (int mt = 0; mt < 2; mt++)
#pragma unroll
                for (int nt = 0; nt < 4; nt++) mma_tf32(acc[mt][nt], a[mt], b[nt]);
        }
        __syncthreads();
    }

    // epilogue
#pragma unroll
    for (int mt = 0; mt < 2; mt++) {
#pragma unroll
        for (int nt = 0; nt < 4; nt++) {
            int r0 = bm + wm * 32 + mt * 16 + gid;
            int c0 = bn + wn * 32 + nt * 8 + tig * 2;
            float bb0 = 0.f, bb1 = 0.f;
            if (bias1) { bb0 += bias1[c0]; bb1 += bias1[c0 + 1]; }
            if (bias2) { bb0 += bias2[c0]; bb1 += bias2[c0 + 1]; }
            if (r0 < NN) {
                float2 o = make_float2(acc[mt][nt][0] + bb0, acc[mt][nt][1] + bb1);
                *(float2*)(Y + (size_t)r0 * D1 + c0) = o;
            }
            if (r0 + 8 < NN) {
                float2 o = make_float2(acc[mt][nt][2] + bb0, acc[mt][nt][3] + bb1);
                *(float2*)(Y + (size_t)(r0 + 8) * D1 + c0) = o;
            }
        }
    }
}

// ---------------- a_s/a_d: warp per node, row read once ----------------
template <int K>
__global__ void k_asad(const float* __restrict__ X) {
    int w = (blockIdx.x * blockDim.x + threadIdx.x) >> 5;
    int l = threadIdx.x & 31;
    if (w >= NN) return;
    const float* xr = X + (size_t)w * K;
    float s[8] = {0.f, 0.f, 0.f, 0.f, 0.f, 0.f, 0.f, 0.f};
#pragma unroll
    for (int q = 0; q < K / 32; q++) {
        int k = l + 32 * q;
        float xv = xr[k];
        float4 v0 = *(const float4*)&g_vcat[k * 8];
        float4 v1 = *(const float4*)&g_vcat[k * 8 + 4];
        s[0] = fmaf(xv, v0.x, s[0]); s[1] = fmaf(xv, v0.y, s[1]);
        s[2] = fmaf(xv, v0.z, s[2]); s[3] = fmaf(xv, v0.w, s[3]);
        s[4] = fmaf(xv, v1.x, s[4]); s[5] = fmaf(xv, v1.y, s[5]);
        s[6] = fmaf(xv, v1.z, s[6]); s[7] = fmaf(xv, v1.w, s[7]);
    }
#pragma unroll
    for (int j = 0; j < 8; j++) {
#pragma unroll
        for (int d = 16; d > 0; d >>= 1) s[j] += __shfl_xor_sync(0xFFFFFFFFu, s[j], d);
    }
    if (l < 8) g_asad[w * 8 + l] = s[l];
}

// ---------------- segmented softmax: thread per node, 4 heads via float4 ----------------
__global__ void k_softmax(const int* __restrict__ src) {
    int n = blockIdx.x * blockDim.x + threadIdx.x;
    if (n >= NN) return;
    int rs = g_rowptr[n], re = g_rowptr[n + 1];
    if (rs == re) return;
    float4 ad = *(const float4*)&g_asad[n * 8 + 4];
    float4 mx = make_float4(-1e30f, -1e30f, -1e30f, -1e30f);
    for (int p = rs; p < re; p++) {
        int eid = g_csr[p];
        int s = src[eid];
        float4 as = *(const float4*)&g_asad[s * 8];
        float4 e;
        e.x = as.x + ad.x; e.y = as.y + ad.y; e.z = as.z + ad.z; e.w = as.w + ad.w;
        e.x = (e.x > 0.f) ? e.x : 0.2f * e.x;
        e.y = (e.y > 0.f) ? e.y : 0.2f * e.y;
        e.z = (e.z > 0.f) ? e.z : 0.2f * e.z;
        e.w = (e.w > 0.f) ? e.w : 0.2f * e.w;
        *(float4*)&g_alpha[(size_t)p * 4] = e;
        mx.x = fmaxf(mx.x, e.x); mx.y = fmaxf(mx.y, e.y);
        mx.z = fmaxf(mx.z, e.z); mx.w = fmaxf(mx.w, e.w);
    }
    float4 den = make_float4(0.f, 0.f, 0.f, 0.f);
    for (int p = rs; p < re; p++) {
        float4 e = *(const float4*)&g_alpha[(size_t)p * 4];
        e.x = __expf(e.x - mx.x); e.y = __expf(e.y - mx.y);
        e.z = __expf(e.z - mx.z); e.w = __expf(e.w - mx.w);
        *(float4*)&g_alpha[(size_t)p * 4] = e;
        den.x += e.x; den.y += e.y; den.z += e.z; den.w += e.w;
    }
    float4 inv;
    inv.x = 1.f / (den.x + 1e-16f); inv.y = 1.f / (den.y + 1e-16f);
    inv.z = 1.f / (den.z + 1e-16f); inv.w = 1.f / (den.w + 1e-16f);
    for (int p = rs; p < re; p++) {
        float4 e = *(const float4*)&g_alpha[(size_t)p * 4];
        e.x *= inv.x; e.y *= inv.y; e.z *= inv.z; e.w *= inv.w;
        *(float4*)&g_alpha[(size_t)p * 4] = e;
    }
}

// ---------------- message aggregation: warp per node, float4 ----------------
__global__ void k_aggregate(const float* __restrict__ xs, float* __restrict__ acc_out,
                            const int* __restrict__ src) {
    int w = (blockIdx.x * blockDim.x + threadIdx.x) >> 5;
    int l = threadIdx.x & 31;
    if (w >= NN) return;
    int rs = g_rowptr[w], re = g_rowptr[w + 1];
    if (rs == re) return;
    int hsel = l >> 4;  // 0 or 1
    float4 acc0 = make_float4(0.f, 0.f, 0.f, 0.f);
    float4 acc1 = make_float4(0.f, 0.f, 0.f, 0.f);
    for (int p = rs; p < re; p++) {
        int eid = g_csr[p];
        int s = src[eid];
        float4 al = *(const float4*)(g_alpha + (size_t)p * 4);
        const float* xr = xs + (size_t)s * D1;
        float a0 = hsel ? al.y : al.x;
        float a1 = hsel ? al.w : al.z;
        float4 v0 = *(const float4*)(xr + l * 4);
        float4 v1 = *(const float4*)(xr + 128 + l * 4);
        acc0.x = fmaf(a0, v0.x, acc0.x); acc0.y = fmaf(a0, v0.y, acc0.y);
        acc0.z = fmaf(a0, v0.z, acc0.z); acc0.w = fmaf(a0, v0.w, acc0.w);
        acc1.x = fmaf(a1, v1.x, acc1.x); acc1.y = fmaf(a1, v1.y, acc1.y);
        acc1.z = fmaf(a1, v1.z, acc1.z); acc1.w = fmaf(a1, v1.w, acc1.w);
    }
    float* o = acc_out + (size_t)w * D1;
    float4 t0 = *(const float4*)(o + l * 4);
    float4 t1 = *(const float4*)(o + 128 + l * 4);
    t0.x += acc0.x; t0.y += acc0.y; t0.z += acc0.z; t0.w += acc0.w;
    t1.x += acc1.x; t1.y += acc1.y; t1.z += acc1.z; t1.w += acc1.w;
    *(float4*)(o + l * 4) = t0;
    *(float4*)(o + 128 + l * 4) = t1;
}

// ---------------- LayerNorm + ReLU ----------------
__global__ void k_lnrelu(const float* __restrict__ in, float* __restrict__ out,
                         const float* __restrict__ gamma, const float* __restrict__ beta) {
    int w = (blockIdx.x * blockDim.x + threadIdx.x) >> 5;
    int l = threadIdx.x & 31;
    if (w >= NN) return;
    const float* r = in + (size_t)w * D1;
    float v[8];
    float s = 0.f, sq = 0.f;
#pragma unroll
    for (int k = 0; k < 8; k++) {
        v[k] = r[l + 32 * k];
        s += v[k];
        sq += v[k] * v[k];
    }
#pragma unroll
    for (int d = 16; d > 0; d >>= 1) {
        s += __shfl_xor_sync(0xFFFFFFFFu, s, d);
        sq += __shfl_xor_sync(0xFFFFFFFFu, sq, d);
    }
    float mean = s * (1.f / D1);
    float var = sq * (1.f / D1) - mean * mean;
    float inv = rsqrtf(var + 1e-5f);
    float* o = out + (size_t)w * D1;
#pragma unroll
    for (int k = 0; k < 8; k++) {
        int c = l + 32 * k;
        float t = (v[k] - mean) * inv * gamma[c] + beta[c];
        o[c] = fmaxf(t, 0.f);
    }
}

// ---------------- host launch ----------------
extern "C" void kernel_launch(void* const* d_in, const int* in_sizes, int n_in,
                              void* d_out, int out_size) {
    const float* x     = (const float*)d_in[0];
    const int*   ei    = (const int*)d_in[1];
    const float* Wsrc1 = (const float*)d_in[2];
    const float* Wdst1 = (const float*)d_in[3];
    const float* atts1 = (const float*)d_in[4];
    const float* attd1 = (const float*)d_in[5];
    const float* b1    = (const float*)d_in[6];
    const float* Wlin1 = (const float*)d_in[7];
    const float* blin1 = (const float*)d_in[8];
    const float* gamma = (const float*)d_in[9];
    const float* beta  = (const float*)d_in[10];
    const float* Wsrc2 = (const float*)d_in[11];
    const float* Wdst2 = (const float*)d_in[12];
    const float* atts2 = (const float*)d_in[13];
    const float* attd2 = (const float*)d_in[14];
    const float* b2    = (const float*)d_in[15];
    const float* Wlin2 = (const float*)d_in[16];
    const float* blin2 = (const float*)d_in[17];
    float* out = (float*)d_out;

    const int* src = ei;
    const int* dst = ei + EE;

    float *xs_p, *acc_p, *h_p;
    cudaGetSymbolAddress((void**)&xs_p, g_xs);
    cudaGetSymbolAddress((void**)&acc_p, g_acc);
    cudaGetSymbolAddress((void**)&h_p, g_h);

    // CSR (graph identical across layers)
    k_zero_deg<<<(NN + 255) / 256, 256>>>();
    k_count<<<(EE + 255) / 256, 256>>>(dst);
    k_scan<<<1, 1024>>>();
    k_fill<<<(EE + 255) / 256, 256>>>(dst);

    dim3 gg((NN + 127) / 128, D1 / 64);

    // ---- layer 1 (K = 128) ----
    k_vcat<<<(DIN * 8 + 255) / 256, 256>>>(Wsrc1, Wdst1, atts1, attd1, DIN);
    k_gemm<DIN><<<gg, 256>>>(x, Wsrc1, nullptr, nullptr, xs_p);
    k_gemm<DIN><<<gg, 256>>>(x, Wlin1, blin1, b1, acc_p);
    k_asad<DIN><<<(NN * 32 + 255) / 256, 256>>>(x);
    k_softmax<<<(NN + 255) / 256, 256>>>(src);
    k_aggregate<<<(NN + 7) / 8, 256>>>(xs_p, acc_p, src);
    k_lnrelu<<<(NN + 7) / 8, 256>>>(acc_p, h_p, gamma, beta);

    // ---- layer 2 (K = 256) ----
    k_vcat<<<(D1 * 8 + 255) / 256, 256>>>(Wsrc2, Wdst2, atts2, attd2, D1);
    k_gemm<D1><<<gg, 256>>>(h_p, Wsrc2, nullptr, nullptr, xs_p);
    k_gemm<D1><<<gg, 256>>>(h_p, Wlin2, blin2, b2, out);
    k_asad<D1><<<(NN * 32 + 255) / 256, 256>>>(h_p);
    k_softmax<<<(NN + 255) / 256, 256>>>(src);
    k_aggregate<<<(NN + 7) / 8, 256>>>(xs_p, out, src);
}

// round 4
// speedup vs baseline: 1.6525x; 1.1478x over previous
#include <cuda_runtime.h>
#include <cuda_bf16.h>
#include <cstdint>

#define NN   50000
#define EE   800000
#define HH   4
#define CC   64
#define DIN  128
#define D1   256

// ---------------- device scratch ----------------
__device__ float g_xs[NN * D1];
__device__ float g_acc[NN * D1];
__device__ float g_h[NN * D1];
__device__ float g_asad[NN * 8];        // per node: a_s[0..3], a_d[0..3]
__device__ float g_alpha[EE * HH];      // CSR-ordered exp values
__device__ float g_invden[NN * 4];      // per node per head: 1/(den+eps)
__device__ float g_vcat[D1 * 8];
__device__ int   g_deg[NN];
__device__ int   g_rowptr[NN + 1];
__device__ int   g_cursor[NN];
__device__ int   g_csr[EE];

// ---------------- CSR build ----------------
__global__ void k_zero_deg() {
    int t = blockIdx.x * blockDim.x + threadIdx.x;
    if (t < NN) g_deg[t] = 0;
}

__global__ void k_count(const int* __restrict__ dst) {
    int t = blockIdx.x * blockDim.x + threadIdx.x;
    if (t < EE) atomicAdd(&g_deg[dst[t]], 1);
}

__global__ void k_scan() {
    __shared__ int sums[1024];
    int t = threadIdx.x;
    const int CH = (NN + 1023) / 1024;
    int base = t * CH;
    int s = 0;
    for (int i = 0; i < CH; i++) {
        int idx = base + i;
        if (idx < NN) s += g_deg[idx];
    }
    int my = s;
    sums[t] = s;
    __syncthreads();
    for (int d = 1; d < 1024; d <<= 1) {
        int v = (t >= d) ? sums[t - d] : 0;
        __syncthreads();
        sums[t] += v;
        __syncthreads();
    }
    if (t == 1023) g_rowptr[NN] = sums[1023];
    int off = sums[t] - my;
    for (int i = 0; i < CH; i++) {
        int idx = base + i;
        if (idx < NN) {
            g_rowptr[idx] = off;
            g_cursor[idx] = off;
            off += g_deg[idx];
        }
    }
}

__global__ void k_fill(const int* __restrict__ dst) {
    int t = blockIdx.x * blockDim.x + threadIdx.x;
    if (t < EE) {
        int d = dst[t];
        int p = atomicAdd(&g_cursor[d], 1);
        g_csr[p] = t;
    }
}

// ---------------- fold att vectors ----------------
__global__ void k_vcat(const float* __restrict__ Wsrc, const float* __restrict__ Wdst,
                       const float* __restrict__ atts, const float* __restrict__ attd, int K) {
    int t = blockIdx.x * blockDim.x + threadIdx.x;
    if (t >= K * 8) return;
    int k = t >> 3, j = t & 7;
    const float* W   = (j < 4) ? Wsrc : Wdst;
    const float* att = (j < 4) ? atts : attd;
    int h = j & 3;
    float s = 0.f;
    for (int c = 0; c < CC; c++) s = fmaf(W[k * D1 + h * CC + c], att[h * CC + c], s);
    g_vcat[t] = s;
}

// ---------------- TF32 helpers ----------------
__device__ __forceinline__ float to_tf32(float x) {
    uint32_t y;
    asm("cvt.rna.tf32.f32 %0, %1;" : "=r"(y) : "f"(x));
    return __uint_as_float(y);
}

__device__ __forceinline__ void mma_tf32(float* d, const uint32_t* a, const uint32_t* b) {
    asm volatile(
        "mma.sync.aligned.m16n8k8.row.col.f32.tf32.tf32.f32 "
        "{%0,%1,%2,%3}, {%4,%5,%6,%7}, {%8,%9}, {%0,%1,%2,%3};"
        : "+f"(d[0]), "+f"(d[1]), "+f"(d[2]), "+f"(d[3])
        : "r"(a[0]), "r"(a[1]), "r"(a[2]), "r"(a[3]), "r"(b[0]), "r"(b[1]));
}

// ---------------- fused dual GEMM (double-buffered, BK=16) ----------------
// Y1 = X @ W1                (no bias)
// Y2 = X @ W2 + b2a + b2b
template <int K>
__global__ void __launch_bounds__(256)
k_dualgemm(const float* __restrict__ X,
           const float* __restrict__ W1, const float* __restrict__ W2,
           const float* __restrict__ b2a, const float* __restrict__ b2b,
           float* __restrict__ Y1, float* __restrict__ Y2) {
    __shared__ float As[2][128][20];
    __shared__ float Bs1[2][16][72];
    __shared__ float Bs2[2][16][72];

    const int tid = threadIdx.x;
    const int bm = blockIdx.x * 128, bn = blockIdx.y * 64;
    const int lane = tid & 31, wid = tid >> 5;
    const int wm = wid >> 1, wn = wid & 1;
    const int gid = lane >> 2, tig = lane & 3;

    // LDG/STS indices
    const int ar0 = tid >> 2, aseg = tid & 3;   // A: rows ar0, ar0+64; k-quad aseg
    const int br = tid >> 4, bseg = tid & 15;   // B: row br, col-quad bseg

    float4 ra[2], rb1, rb2;
    float acc[2][2][4][4];
#pragma unroll
    for (int m = 0; m < 2; m++)
#pragma unroll
        for (int i = 0; i < 2; i++)
#pragma unroll
            for (int j = 0; j < 4; j++)
#pragma unroll
                for (int q = 0; q < 4; q++) acc[m][i][j][q] = 0.f;

    const int KT = K / 16;

    // prologue: load tile 0
    {
#pragma unroll
        for (int i = 0; i < 2; i++) {
            int gr = bm + ar0 + i * 64;
            float4 v = make_float4(0.f, 0.f, 0.f, 0.f);
            if (gr < NN) v = *(const float4*)(X + (size_t)gr * K + aseg * 4);
            ra[i] = v;
        }
        rb1 = *(const float4*)(W1 + (size_t)br * D1 + bn + bseg * 4);
        rb2 = *(const float4*)(W2 + (size_t)br * D1 + bn + bseg * 4);
#pragma unroll
        for (int i = 0; i < 2; i++) {
            float4 v = ra[i];
            v.x = to_tf32(v.x); v.y = to_tf32(v.y); v.z = to_tf32(v.z); v.w = to_tf32(v.w);
            *(float4*)&As[0][ar0 + i * 64][aseg * 4] = v;
        }
        float4 v = rb1;
        v.x = to_tf32(v.x); v.y = to_tf32(v.y); v.z = to_tf32(v.z); v.w = to_tf32(v.w);
        *(float4*)&Bs1[0][br][bseg * 4] = v;
        v = rb2;
        v.x = to_tf32(v.x); v.y = to_tf32(v.y); v.z = to_tf32(v.z); v.w = to_tf32(v.w);
        *(float4*)&Bs2[0][br][bseg * 4] = v;
    }
    __syncthreads();

    for (int kt = 0; kt < KT; kt++) {
        const int cur = kt & 1;
        const int nxt = cur ^ 1;
        if (kt + 1 < KT) {
            int k0 = (kt + 1) * 16;
#pragma unroll
            for (int i = 0; i < 2; i++) {
                int gr = bm + ar0 + i * 64;
                float4 v = make_float4(0.f, 0.f, 0.f, 0.f);
                if (gr < NN) v = *(const float4*)(X + (size_t)gr * K + k0 + aseg * 4);
                ra[i] = v;
            }
            rb1 = *(const float4*)(W1 + (size_t)(k0 + br) * D1 + bn + bseg * 4);
            rb2 = *(const float4*)(W2 + (size_t)(k0 + br) * D1 + bn + bseg * 4);
        }

#pragma unroll
        for (int ks = 0; ks < 16; ks += 8) {
            uint32_t a[2][4], bf1[4][2], bf2[4][2];
#pragma unroll
            for (int mt = 0; mt < 2; mt++) {
                int mr = wm * 32 + mt * 16 + gid;
                a[mt][0] = __float_as_uint(As[cur][mr][ks + tig]);
                a[mt][1] = __float_as_uint(As[cur][mr + 8][ks + tig]);
                a[mt][2] = __float_as_uint(As[cur][mr][ks + tig + 4]);
                a[mt][3] = __float_as_uint(As[cur][mr + 8][ks + tig + 4]);
            }
#pragma unroll
            for (int nt = 0; nt < 4; nt++) {
                int nc = wn * 32 + nt * 8 + gid;
                bf1[nt][0] = __float_as_uint(Bs1[cur][ks + tig][nc]);
                bf1[nt][1] = __float_as_uint(Bs1[cur][ks + tig + 4][nc]);
                bf2[nt][0] = __float_as_uint(Bs2[cur][ks + tig][nc]);
                bf2[nt][1] = __float_as_uint(Bs2[cur][ks + tig + 4][nc]);
            }
#pragma unroll
            for (int mt = 0; mt < 2; mt++)
#pragma unroll
                for (int nt = 0; nt < 4; nt++) {
                    mma_tf32(acc[0][mt][nt], a[mt], bf1[nt]);
                    mma_tf32(acc[1][mt][nt], a[mt], bf2[nt]);
                }
        }

        if (kt + 1 < KT) {
#pragma unroll
            for (int i = 0; i < 2; i++) {
                float4 v = ra[i];
                v.x = to_tf32(v.x); v.y = to_tf32(v.y); v.z = to_tf32(v.z); v.w = to_tf32(v.w);
                *(float4*)&As[nxt][ar0 + i * 64][aseg * 4] = v;
            }
            float4 v = rb1;
            v.x = to_tf32(v.x); v.y = to_tf32(v.y); v.z = to_tf32(v.z); v.w = to_tf32(v.w);
            *(float4*)&Bs1[nxt][br][bseg * 4] = v;
            v = rb2;
            v.x = to_tf32(v.x); v.y = to_tf32(v.y); v.z = to_tf32(v.z); v.w = to_tf32(v.w);
            *(float4*)&Bs2[nxt][br][bseg * 4] = v;
        }
        __syncthreads();
    }

    // epilogue
#pragma unroll
    for (int mt = 0; mt < 2; mt++) {
#pragma unroll
        for (int nt = 0; nt < 4; nt++) {
            int r0 = bm + wm * 32 + mt * 16 + gid;
            int c0 = bn + wn * 32 + nt * 8 + tig * 2;
            float bb0 = b2a[c0] + b2b[c0];
            float bb1 = b2a[c0 + 1] + b2b[c0 + 1];
            if (r0 < NN) {
                *(float2*)(Y1 + (size_t)r0 * D1 + c0) =
                    make_float2(acc[0][mt][nt][0], acc[0][mt][nt][1]);
                *(float2*)(Y2 + (size_t)r0 * D1 + c0) =
                    make_float2(acc[1][mt][nt][0] + bb0, acc[1][mt][nt][1] + bb1);
            }
            if (r0 + 8 < NN) {
                *(float2*)(Y1 + (size_t)(r0 + 8) * D1 + c0) =
                    make_float2(acc[0][mt][nt][2], acc[0][mt][nt][3]);
                *(float2*)(Y2 + (size_t)(r0 + 8) * D1 + c0) =
                    make_float2(acc[1][mt][nt][2] + bb0, acc[1][mt][nt][3] + bb1);
            }
        }
    }
}

// ---------------- a_s/a_d: warp per node ----------------
template <int K>
__global__ void k_asad(const float* __restrict__ X) {
    int w = (blockIdx.x * blockDim.x + threadIdx.x) >> 5;
    int l = threadIdx.x & 31;
    if (w >= NN) return;
    const float* xr = X + (size_t)w * K;
    float s[8] = {0.f, 0.f, 0.f, 0.f, 0.f, 0.f, 0.f, 0.f};
#pragma unroll
    for (int q = 0; q < K / 32; q++) {
        int k = l + 32 * q;
        float xv = xr[k];
        float4 v0 = *(const float4*)&g_vcat[k * 8];
        float4 v1 = *(const float4*)&g_vcat[k * 8 + 4];
        s[0] = fmaf(xv, v0.x, s[0]); s[1] = fmaf(xv, v0.y, s[1]);
        s[2] = fmaf(xv, v0.z, s[2]); s[3] = fmaf(xv, v0.w, s[3]);
        s[4] = fmaf(xv, v1.x, s[4]); s[5] = fmaf(xv, v1.y, s[5]);
        s[6] = fmaf(xv, v1.z, s[6]); s[7] = fmaf(xv, v1.w, s[7]);
    }
#pragma unroll
    for (int j = 0; j < 8; j++) {
#pragma unroll
        for (int d = 16; d > 0; d >>= 1) s[j] += __shfl_xor_sync(0xFFFFFFFFu, s[j], d);
    }
    if (l < 8) g_asad[w * 8 + l] = s[l];
}

// ---------------- softmax: 2 passes; stores ex and 1/(den+eps) ----------------
__global__ void k_softmax(const int* __restrict__ src) {
    int n = blockIdx.x * blockDim.x + threadIdx.x;
    if (n >= NN) return;
    int rs = g_rowptr[n], re = g_rowptr[n + 1];
    if (rs == re) {
        *(float4*)&g_invden[n * 4] = make_float4(0.f, 0.f, 0.f, 0.f);
        return;
    }
    float4 ad = *(const float4*)&g_asad[n * 8 + 4];
    float4 mx = make_float4(-1e30f, -1e30f, -1e30f, -1e30f);
    for (int p = rs; p < re; p++) {
        int eid = g_csr[p];
        int s = src[eid];
        float4 as = *(const float4*)&g_asad[s * 8];
        float4 e;
        e.x = as.x + ad.x; e.y = as.y + ad.y; e.z = as.z + ad.z; e.w = as.w + ad.w;
        e.x = (e.x > 0.f) ? e.x : 0.2f * e.x;
        e.y = (e.y > 0.f) ? e.y : 0.2f * e.y;
        e.z = (e.z > 0.f) ? e.z : 0.2f * e.z;
        e.w = (e.w > 0.f) ? e.w : 0.2f * e.w;
        *(float4*)&g_alpha[(size_t)p * 4] = e;
        mx.x = fmaxf(mx.x, e.x); mx.y = fmaxf(mx.y, e.y);
        mx.z = fmaxf(mx.z, e.z); mx.w = fmaxf(mx.w, e.w);
    }
    float4 den = make_float4(0.f, 0.f, 0.f, 0.f);
    for (int p = rs; p < re; p++) {
        float4 e = *(const float4*)&g_alpha[(size_t)p * 4];
        e.x = __expf(e.x - mx.x); e.y = __expf(e.y - mx.y);
        e.z = __expf(e.z - mx.z); e.w = __expf(e.w - mx.w);
        *(float4*)&g_alpha[(size_t)p * 4] = e;
        den.x += e.x; den.y += e.y; den.z += e.z; den.w += e.w;
    }
    float4 inv;
    inv.x = 1.f / (den.x + 1e-16f); inv.y = 1.f / (den.y + 1e-16f);
    inv.z = 1.f / (den.z + 1e-16f); inv.w = 1.f / (den.w + 1e-16f);
    *(float4*)&g_invden[n * 4] = inv;
}

// ---------------- layer-1: aggregate + skip + LayerNorm + ReLU (warp/node) ----------------
__global__ void k_agg_ln(const float* __restrict__ xs, const float* __restrict__ skip,
                         float* __restrict__ hout,
                         const int* __restrict__ src,
                         const float* __restrict__ gamma, const float* __restrict__ beta) {
    int w = (blockIdx.x * blockDim.x + threadIdx.x) >> 5;
    int l = threadIdx.x & 31;
    if (w >= NN) return;
    int rs = g_rowptr[w], re = g_rowptr[w + 1];
    int hsel = l >> 4;
    float4 m0 = make_float4(0.f, 0.f, 0.f, 0.f);
    float4 m1 = make_float4(0.f, 0.f, 0.f, 0.f);
    for (int p = rs; p < re; p++) {
        int eid = g_csr[p];
        int s = src[eid];
        float4 al = *(const float4*)(g_alpha + (size_t)p * 4);
        const float* xr = xs + (size_t)s * D1;
        float a0 = hsel ? al.y : al.x;
        float a1 = hsel ? al.w : al.z;
        float4 v0 = *(const float4*)(xr + l * 4);
        float4 v1 = *(const float4*)(xr + 128 + l * 4);
        m0.x = fmaf(a0, v0.x, m0.x); m0.y = fmaf(a0, v0.y, m0.y);
        m0.z = fmaf(a0, v0.z, m0.z); m0.w = fmaf(a0, v0.w, m0.w);
        m1.x = fmaf(a1, v1.x, m1.x); m1.y = fmaf(a1, v1.y, m1.y);
        m1.z = fmaf(a1, v1.z, m1.z); m1.w = fmaf(a1, v1.w, m1.w);
    }
    float4 inv4 = *(const float4*)&g_invden[w * 4];
    float i0 = hsel ? inv4.y : inv4.x;
    float i1 = hsel ? inv4.w : inv4.z;
    m0.x *= i0; m0.y *= i0; m0.z *= i0; m0.w *= i0;
    m1.x *= i1; m1.y *= i1; m1.z *= i1; m1.w *= i1;

    const float* sk = skip + (size_t)w * D1;
    float4 s0 = *(const float4*)(sk + l * 4);
    float4 s1 = *(const float4*)(sk + 128 + l * 4);
    float v[8] = {s0.x + m0.x, s0.y + m0.y, s0.z + m0.z, s0.w + m0.w,
                  s1.x + m1.x, s1.y + m1.y, s1.z + m1.z, s1.w + m1.w};
    float sm = 0.f, sq = 0.f;
#pragma unroll
    for (int k = 0; k < 8; k++) { sm += v[k]; sq += v[k] * v[k]; }
#pragma unroll
    for (int d = 16; d > 0; d >>= 1) {
        sm += __shfl_xor_sync(0xFFFFFFFFu, sm, d);
        sq += __shfl_xor_sync(0xFFFFFFFFu, sq, d);
    }
    float mean = sm * (1.f / D1);
    float var = sq * (1.f / D1) - mean * mean;
    float rstd = rsqrtf(var + 1e-5f);
    float4 g0 = *(const float4*)(gamma + l * 4);
    float4 g1 = *(const float4*)(gamma + 128 + l * 4);
    float4 be0 = *(const float4*)(beta + l * 4);
    float4 be1 = *(const float4*)(beta + 128 + l * 4);
    float* o = hout + (size_t)w * D1;
    float4 o0, o1;
    o0.x = fmaxf((v[0] - mean) * rstd * g0.x + be0.x, 0.f);
    o0.y = fmaxf((v[1] - mean) * rstd * g0.y + be0.y, 0.f);
    o0.z = fmaxf((v[2] - mean) * rstd * g0.z + be0.z, 0.f);
    o0.w = fmaxf((v[3] - mean) * rstd * g0.w + be0.w, 0.f);
    o1.x = fmaxf((v[4] - mean) * rstd * g1.x + be1.x, 0.f);
    o1.y = fmaxf((v[5] - mean) * rstd * g1.y + be1.y, 0.f);
    o1.z = fmaxf((v[6] - mean) * rstd * g1.z + be1.z, 0.f);
    o1.w = fmaxf((v[7] - mean) * rstd * g1.w + be1.w, 0.f);
    *(float4*)(o + l * 4) = o0;
    *(float4*)(o + 128 + l * 4) = o1;
}

// ---------------- layer-2: aggregate into out (+= msg * inv) ----------------
__global__ void k_agg2(const float* __restrict__ xs, float* __restrict__ out,
                       const int* __restrict__ src) {
    int w = (blockIdx.x * blockDim.x + threadIdx.x) >> 5;
    int l = threadIdx.x & 31;
    if (w >= NN) return;
    int rs = g_rowptr[w], re = g_rowptr[w + 1];
    if (rs == re) return;
    int hsel = l >> 4;
    float4 m0 = make_float4(0.f, 0.f, 0.f, 0.f);
    float4 m1 = make_float4(0.f, 0.f, 0.f, 0.f);
    for (int p = rs; p < re; p++) {
        int eid = g_csr[p];
        int s = src[eid];
        float4 al = *(const float4*)(g_alpha + (size_t)p * 4);
        const float* xr = xs + (size_t)s * D1;
        float a0 = hsel ? al.y : al.x;
        float a1 = hsel ? al.w : al.z;
        float4 v0 = *(const float4*)(xr + l * 4);
        float4 v1 = *(const float4*)(xr + 128 + l * 4);
        m0.x = fmaf(a0, v0.x, m0.x); m0.y = fmaf(a0, v0.y, m0.y);
        m0.z = fmaf(a0, v0.z, m0.z); m0.w = fmaf(a0, v0.w, m0.w);
        m1.x = fmaf(a1, v1.x, m1.x); m1.y = fmaf(a1, v1.y, m1.y);
        m1.z = fmaf(a1, v1.z, m1.z); m1.w = fmaf(a1, v1.w, m1.w);
    }
    float4 inv4 = *(const float4*)&g_invden[w * 4];
    float i0 = hsel ? inv4.y : inv4.x;
    float i1 = hsel ? inv4.w : inv4.z;
    float* o = out + (size_t)w * D1;
    float4 t0 = *(const float4*)(o + l * 4);
    float4 t1 = *(const float4*)(o + 128 + l * 4);
    t0.x = fmaf(m0.x, i0, t0.x); t0.y = fmaf(m0.y, i0, t0.y);
    t0.z = fmaf(m0.z, i0, t0.z); t0.w = fmaf(m0.w, i0, t0.w);
    t1.x = fmaf(m1.x, i1, t1.x); t1.y = fmaf(m1.y, i1, t1.y);
    t1.z = fmaf(m1.z, i1, t1.z); t1.w = fmaf(m1.w, i1, t1.w);
    *(float4*)(o + l * 4) = t0;
    *(float4*)(o + 128 + l * 4) = t1;
}

// ---------------- host launch ----------------
extern "C" void kernel_launch(void* const* d_in, const int* in_sizes, int n_in,
                              void* d_out, int out_size) {
    const float* x     = (const float*)d_in[0];
    const int*   ei    = (const int*)d_in[1];
    const float* Wsrc1 = (const float*)d_in[2];
    const float* Wdst1 = (const float*)d_in[3];
    const float* atts1 = (const float*)d_in[4];
    const float* attd1 = (const float*)d_in[5];
    const float* b1    = (const float*)d_in[6];
    const float* Wlin1 = (const float*)d_in[7];
    const float* blin1 = (const float*)d_in[8];
    const float* gamma = (const float*)d_in[9];
    const float* beta  = (const float*)d_in[10];
    const float* Wsrc2 = (const float*)d_in[11];
    const float* Wdst2 = (const float*)d_in[12];
    const float* atts2 = (const float*)d_in[13];
    const float* attd2 = (const float*)d_in[14];
    const float* b2    = (const float*)d_in[15];
    const float* Wlin2 = (const float*)d_in[16];
    const float* blin2 = (const float*)d_in[17];
    float* out = (float*)d_out;

    const int* src = ei;
    const int* dst = ei + EE;

    float *xs_p, *acc_p, *h_p;
    cudaGetSymbolAddress((void**)&xs_p, g_xs);
    cudaGetSymbolAddress((void**)&acc_p, g_acc);
    cudaGetSymbolAddress((void**)&h_p, g_h);

    // CSR (graph identical across layers)
    k_zero_deg<<<(NN + 255) / 256, 256>>>();
    k_count<<<(EE + 255) / 256, 256>>>(dst);
    k_scan<<<1, 1024>>>();
    k_fill<<<(EE + 255) / 256, 256>>>(dst);

    dim3 gg((NN + 127) / 128, D1 / 64);

    // ---- layer 1 (K = 128) ----
    k_vcat<<<(DIN * 8 + 255) / 256, 256>>>(Wsrc1, Wdst1, atts1, attd1, DIN);
    k_dualgemm<DIN><<<gg, 256>>>(x, Wsrc1, Wlin1, blin1, b1, xs_p, acc_p);
    k_asad<DIN><<<(NN * 32 + 255) / 256, 256>>>(x);
    k_softmax<<<(NN + 255) / 256, 256>>>(src);
    k_agg_ln<<<(NN + 7) / 8, 256>>>(xs_p, acc_p, h_p, src, gamma, beta);

    // ---- layer 2 (K = 256) ----
    k_vcat<<<(D1 * 8 + 255) / 256, 256>>>(Wsrc2, Wdst2, atts2, attd2, D1);
    k_dualgemm<D1><<<gg, 256>>>(h_p, Wsrc2, Wlin2, blin2, b2, xs_p, out);
    k_asad<D1><<<(NN * 32 + 255) / 256, 256>>>(h_p);
    k_softmax<<<(NN + 255) / 256, 256>>>(src);
    k_agg2<<<(NN + 7) / 8, 256>>>(xs_p, out, src);
}

// round 5
// speedup vs baseline: 1.8283x; 1.1064x over previous
#include <cuda_runtime.h>
#include <cuda_bf16.h>
#include <cstdint>

#define NN   50000
#define EE   800000
#define HH   4
#define CC   64
#define DIN  128
#define D1   256

// ---------------- device scratch ----------------
__device__ float g_xs[NN * D1];
__device__ float g_acc[NN * D1];
__device__ float g_h[NN * D1];
__device__ float g_asad[NN * 8];        // per node: a_s[0..3], a_d[0..3]
__device__ float g_alpha[EE * HH];      // CSR-ordered exp(e) values
__device__ float g_vcat[D1 * 8];
__device__ int   g_deg[NN];
__device__ int   g_rowptr[NN + 1];
__device__ int   g_cursor[NN];
__device__ int   g_pos[EE];             // eid -> CSR position
__device__ int   g_csrc[EE];            // CSR position -> src node

// ---------------- CSR build ----------------
__global__ void k_zero_deg() {
    int t = blockIdx.x * blockDim.x + threadIdx.x;
    if (t < NN) g_deg[t] = 0;
}

__global__ void k_count(const int* __restrict__ dst) {
    int t = blockIdx.x * blockDim.x + threadIdx.x;
    if (t < EE) atomicAdd(&g_deg[dst[t]], 1);
}

__global__ void k_scan() {
    __shared__ int sums[1024];
    int t = threadIdx.x;
    const int CH = (NN + 1023) / 1024;
    int base = t * CH;
    int s = 0;
    for (int i = 0; i < CH; i++) {
        int idx = base + i;
        if (idx < NN) s += g_deg[idx];
    }
    int my = s;
    sums[t] = s;
    __syncthreads();
    for (int d = 1; d < 1024; d <<= 1) {
        int v = (t >= d) ? sums[t - d] : 0;
        __syncthreads();
        sums[t] += v;
        __syncthreads();
    }
    if (t == 1023) g_rowptr[NN] = sums[1023];
    int off = sums[t] - my;
    for (int i = 0; i < CH; i++) {
        int idx = base + i;
        if (idx < NN) {
            g_rowptr[idx] = off;
            g_cursor[idx] = off;
            off += g_deg[idx];
        }
    }
}

__global__ void k_fill(const int* __restrict__ dst, const int* __restrict__ src) {
    int t = blockIdx.x * blockDim.x + threadIdx.x;
    if (t < EE) {
        int d = dst[t];
        int p = atomicAdd(&g_cursor[d], 1);
        g_pos[t] = p;
        g_csrc[p] = src[t];
    }
}

// ---------------- fold att vectors ----------------
__global__ void k_vcat(const float* __restrict__ Wsrc, const float* __restrict__ Wdst,
                       const float* __restrict__ atts, const float* __restrict__ attd, int K) {
    int t = blockIdx.x * blockDim.x + threadIdx.x;
    if (t >= K * 8) return;
    int k = t >> 3, j = t & 7;
    const float* W   = (j < 4) ? Wsrc : Wdst;
    const float* att = (j < 4) ? atts : attd;
    int h = j & 3;
    float s = 0.f;
    for (int c = 0; c < CC; c++) s = fmaf(W[k * D1 + h * CC + c], att[h * CC + c], s);
    g_vcat[t] = s;
}

// ---------------- TF32 helpers ----------------
__device__ __forceinline__ float to_tf32(float x) {
    uint32_t y;
    asm("cvt.rna.tf32.f32 %0, %1;" : "=r"(y) : "f"(x));
    return __uint_as_float(y);
}

__device__ __forceinline__ void mma_tf32(float* d, const uint32_t* a, const uint32_t* b) {
    asm volatile(
        "mma.sync.aligned.m16n8k8.row.col.f32.tf32.tf32.f32 "
        "{%0,%1,%2,%3}, {%4,%5,%6,%7}, {%8,%9}, {%0,%1,%2,%3};"
        : "+f"(d[0]), "+f"(d[1]), "+f"(d[2]), "+f"(d[3])
        : "r"(a[0]), "r"(a[1]), "r"(a[2]), "r"(a[3]), "r"(b[0]), "r"(b[1]));
}

// ---------------- fused dual GEMM (double-buffered, BK=16) ----------------
// Y1 = X @ W1                (no bias)
// Y2 = X @ W2 + b2a + b2b
template <int K>
__global__ void __launch_bounds__(256)
k_dualgemm(const float* __restrict__ X,
           const float* __restrict__ W1, const float* __restrict__ W2,
           const float* __restrict__ b2a, const float* __restrict__ b2b,
           float* __restrict__ Y1, float* __restrict__ Y2) {
    __shared__ float As[2][128][20];
    __shared__ float Bs1[2][16][72];
    __shared__ float Bs2[2][16][72];

    const int tid = threadIdx.x;
    const int bm = blockIdx.x * 128, bn = blockIdx.y * 64;
    const int lane = tid & 31, wid = tid >> 5;
    const int wm = wid >> 1, wn = wid & 1;
    const int gid = lane >> 2, tig = lane & 3;

    const int ar0 = tid >> 2, aseg = tid & 3;
    const int br = tid >> 4, bseg = tid & 15;

    float4 ra[2], rb1, rb2;
    float acc[2][2][4][4];
#pragma unroll
    for (int m = 0; m < 2; m++)
#pragma unroll
        for (int i = 0; i < 2; i++)
#pragma unroll
            for (int j = 0; j < 4; j++)
#pragma unroll
                for (int q = 0; q < 4; q++) acc[m][i][j][q] = 0.f;

    const int KT = K / 16;

    {
#pragma unroll
        for (int i = 0; i < 2; i++) {
            int gr = bm + ar0 + i * 64;
            float4 v = make_float4(0.f, 0.f, 0.f, 0.f);
            if (gr < NN) v = *(const float4*)(X + (size_t)gr * K + aseg * 4);
            ra[i] = v;
        }
        rb1 = *(const float4*)(W1 + (size_t)br * D1 + bn + bseg * 4);
        rb2 = *(const float4*)(W2 + (size_t)br * D1 + bn + bseg * 4);
#pragma unroll
        for (int i = 0; i < 2; i++) {
            float4 v = ra[i];
            v.x = to_tf32(v.x); v.y = to_tf32(v.y); v.z = to_tf32(v.z); v.w = to_tf32(v.w);
            *(float4*)&As[0][ar0 + i * 64][aseg * 4] = v;
        }
        float4 v = rb1;
        v.x = to_tf32(v.x); v.y = to_tf32(v.y); v.z = to_tf32(v.z); v.w = to_tf32(v.w);
        *(float4*)&Bs1[0][br][bseg * 4] = v;
        v = rb2;
        v.x = to_tf32(v.x); v.y = to_tf32(v.y); v.z = to_tf32(v.z); v.w = to_tf32(v.w);
        *(float4*)&Bs2[0][br][bseg * 4] = v;
    }
    __syncthreads();

    for (int kt = 0; kt < KT; kt++) {
        const int cur = kt & 1;
        const int nxt = cur ^ 1;
        if (kt + 1 < KT) {
            int k0 = (kt + 1) * 16;
#pragma unroll
            for (int i = 0; i < 2; i++) {
                int gr = bm + ar0 + i * 64;
                float4 v = make_float4(0.f, 0.f, 0.f, 0.f);
                if (gr < NN) v = *(const float4*)(X + (size_t)gr * K + k0 + aseg * 4);
                ra[i] = v;
            }
            rb1 = *(const float4*)(W1 + (size_t)(k0 + br) * D1 + bn + bseg * 4);
            rb2 = *(const float4*)(W2 + (size_t)(k0 + br) * D1 + bn + bseg * 4);
        }

#pragma unroll
        for (int ks = 0; ks < 16; ks += 8) {
            uint32_t a[2][4], bf1[4][2], bf2[4][2];
#pragma unroll
            for (int mt = 0; mt < 2; mt++) {
                int mr = wm * 32 + mt * 16 + gid;
                a[mt][0] = __float_as_uint(As[cur][mr][ks + tig]);
                a[mt][1] = __float_as_uint(As[cur][mr + 8][ks + tig]);
                a[mt][2] = __float_as_uint(As[cur][mr][ks + tig + 4]);
                a[mt][3] = __float_as_uint(As[cur][mr + 8][ks + tig + 4]);
            }
#pragma unroll
            for (int nt = 0; nt < 4; nt++) {
                int nc = wn * 32 + nt * 8 + gid;
                bf1[nt][0] = __float_as_uint(Bs1[cur][ks + tig][nc]);
                bf1[nt][1] = __float_as_uint(Bs1[cur][ks + tig + 4][nc]);
                bf2[nt][0] = __float_as_uint(Bs2[cur][ks + tig][nc]);
                bf2[nt][1] = __float_as_uint(Bs2[cur][ks + tig + 4][nc]);
            }
#pragma unroll
            for (int mt = 0; mt < 2; mt++)
#pragma unroll
                for (int nt = 0; nt < 4; nt++) {
                    mma_tf32(acc[0][mt][nt], a[mt], bf1[nt]);
                    mma_tf32(acc[1][mt][nt], a[mt], bf2[nt]);
                }
        }

        if (kt + 1 < KT) {
#pragma unroll
            for (int i = 0; i < 2; i++) {
                float4 v = ra[i];
                v.x = to_tf32(v.x); v.y = to_tf32(v.y); v.z = to_tf32(v.z); v.w = to_tf32(v.w);
                *(float4*)&As[nxt][ar0 + i * 64][aseg * 4] = v;
            }
            float4 v = rb1;
            v.x = to_tf32(v.x); v.y = to_tf32(v.y); v.z = to_tf32(v.z); v.w = to_tf32(v.w);
            *(float4*)&Bs1[nxt][br][bseg * 4] = v;
            v = rb2;
            v.x = to_tf32(v.x); v.y = to_tf32(v.y); v.z = to_tf32(v.z); v.w = to_tf32(v.w);
            *(float4*)&Bs2[nxt][br][bseg * 4] = v;
        }
        __syncthreads();
    }

#pragma unroll
    for (int mt = 0; mt < 2; mt++) {
#pragma unroll
        for (int nt = 0; nt < 4; nt++) {
            int r0 = bm + wm * 32 + mt * 16 + gid;
            int c0 = bn + wn * 32 + nt * 8 + tig * 2;
            float bb0 = b2a[c0] + b2b[c0];
            float bb1 = b2a[c0 + 1] + b2b[c0 + 1];
            if (r0 < NN) {
                *(float2*)(Y1 + (size_t)r0 * D1 + c0) =
                    make_float2(acc[0][mt][nt][0], acc[0][mt][nt][1]);
                *(float2*)(Y2 + (size_t)r0 * D1 + c0) =
                    make_float2(acc[1][mt][nt][0] + bb0, acc[1][mt][nt][1] + bb1);
            }
            if (r0 + 8 < NN) {
                *(float2*)(Y1 + (size_t)(r0 + 8) * D1 + c0) =
                    make_float2(acc[0][mt][nt][2], acc[0][mt][nt][3]);
                *(float2*)(Y2 + (size_t)(r0 + 8) * D1 + c0) =
                    make_float2(acc[1][mt][nt][2] + bb0, acc[1][mt][nt][3] + bb1);
            }
        }
    }
}

// ---------------- a_s/a_d: warp per node ----------------
template <int K>
__global__ void k_asad(const float* __restrict__ X) {
    int w = (blockIdx.x * blockDim.x + threadIdx.x) >> 5;
    int l = threadIdx.x & 31;
    if (w >= NN) return;
    const float* xr = X + (size_t)w * K;
    float s[8] = {0.f, 0.f, 0.f, 0.f, 0.f, 0.f, 0.f, 0.f};
#pragma unroll
    for (int q = 0; q < K / 32; q++) {
        int k = l + 32 * q;
        float xv = xr[k];
        float4 v0 = *(const float4*)&g_vcat[k * 8];
        float4 v1 = *(const float4*)&g_vcat[k * 8 + 4];
        s[0] = fmaf(xv, v0.x, s[0]); s[1] = fmaf(xv, v0.y, s[1]);
        s[2] = fmaf(xv, v0.z, s[2]); s[3] = fmaf(xv, v0.w, s[3]);
        s[4] = fmaf(xv, v1.x, s[4]); s[5] = fmaf(xv, v1.y, s[5]);
        s[6] = fmaf(xv, v1.z, s[6]); s[7] = fmaf(xv, v1.w, s[7]);
    }
#pragma unroll
    for (int j = 0; j < 8; j++) {
#pragma unroll
        for (int d = 16; d > 0; d >>= 1) s[j] += __shfl_xor_sync(0xFFFFFFFFu, s[j], d);
    }
    if (l < 8) g_asad[w * 8 + l] = s[l];
}

// ---------------- edge-parallel exp(leaky(a_s+a_d)), written in CSR order ----------------
// Softmax is shift invariant; scores here are O(1) so exp cannot overflow, and
// the eps-term difference vs the max-subtracted reference is ~1e-15 relative.
__global__ void k_edge_ex(const int* __restrict__ src, const int* __restrict__ dst) {
    int t = blockIdx.x * blockDim.x + threadIdx.x;
    if (t >= EE) return;
    int s = src[t], d = dst[t];
    float4 as = *(const float4*)&g_asad[s * 8];
    float4 ad = *(const float4*)&g_asad[d * 8 + 4];
    float4 e;
    e.x = as.x + ad.x; e.y = as.y + ad.y; e.z = as.z + ad.z; e.w = as.w + ad.w;
    e.x = (e.x > 0.f) ? e.x : 0.2f * e.x;
    e.y = (e.y > 0.f) ? e.y : 0.2f * e.y;
    e.z = (e.z > 0.f) ? e.z : 0.2f * e.z;
    e.w = (e.w > 0.f) ? e.w : 0.2f * e.w;
    e.x = __expf(e.x); e.y = __expf(e.y); e.z = __expf(e.z); e.w = __expf(e.w);
    *(float4*)&g_alpha[(size_t)g_pos[t] * 4] = e;
}

// ---------------- layer-1: aggregate + den + skip + LayerNorm + ReLU (warp/node) ----------------
__global__ void k_agg_ln(const float* __restrict__ xs, const float* __restrict__ skip,
                         float* __restrict__ hout,
                         const float* __restrict__ gamma, const float* __restrict__ beta) {
    int w = (blockIdx.x * blockDim.x + threadIdx.x) >> 5;
    int l = threadIdx.x & 31;
    if (w >= NN) return;
    int rs = g_rowptr[w], re = g_rowptr[w + 1];
    int hsel = l >> 4;
    float4 m0 = make_float4(0.f, 0.f, 0.f, 0.f);
    float4 m1 = make_float4(0.f, 0.f, 0.f, 0.f);
    float den0 = 0.f, den1 = 0.f;
    for (int p = rs; p < re; p++) {
        int s = g_csrc[p];
        float4 al = *(const float4*)(g_alpha + (size_t)p * 4);
        const float* xr = xs + (size_t)s * D1;
        float a0 = hsel ? al.y : al.x;
        float a1 = hsel ? al.w : al.z;
        den0 += a0; den1 += a1;
        float4 v0 = *(const float4*)(xr + l * 4);
        float4 v1 = *(const float4*)(xr + 128 + l * 4);
        m0.x = fmaf(a0, v0.x, m0.x); m0.y = fmaf(a0, v0.y, m0.y);
        m0.z = fmaf(a0, v0.z, m0.z); m0.w = fmaf(a0, v0.w, m0.w);
        m1.x = fmaf(a1, v1.x, m1.x); m1.y = fmaf(a1, v1.y, m1.y);
        m1.z = fmaf(a1, v1.z, m1.z); m1.w = fmaf(a1, v1.w, m1.w);
    }
    float i0 = 1.f / (den0 + 1e-16f);
    float i1 = 1.f / (den1 + 1e-16f);
    m0.x *= i0; m0.y *= i0; m0.z *= i0; m0.w *= i0;
    m1.x *= i1; m1.y *= i1; m1.z *= i1; m1.w *= i1;

    const float* sk = skip + (size_t)w * D1;
    float4 s0 = *(const float4*)(sk + l * 4);
    float4 s1 = *(const float4*)(sk + 128 + l * 4);
    float v[8] = {s0.x + m0.x, s0.y + m0.y, s0.z + m0.z, s0.w + m0.w,
                  s1.x + m1.x, s1.y + m1.y, s1.z + m1.z, s1.w + m1.w};
    float sm = 0.f, sq = 0.f;
#pragma unroll
    for (int k = 0; k < 8; k++) { sm += v[k]; sq += v[k] * v[k]; }
#pragma unroll
    for (int d = 16; d > 0; d >>= 1) {
        sm += __shfl_xor_sync(0xFFFFFFFFu, sm, d);
        sq += __shfl_xor_sync(0xFFFFFFFFu, sq, d);
    }
    float mean = sm * (1.f / D1);
    float var = sq * (1.f / D1) - mean * mean;
    float rstd = rsqrtf(var + 1e-5f);
    float4 g0 = *(const float4*)(gamma + l * 4);
    float4 g1 = *(const float4*)(gamma + 128 + l * 4);
    float4 be0 = *(const float4*)(beta + l * 4);
    float4 be1 = *(const float4*)(beta + 128 + l * 4);
    float* o = hout + (size_t)w * D1;
    float4 o0, o1;
    o0.x = fmaxf((v[0] - mean) * rstd * g0.x + be0.x, 0.f);
    o0.y = fmaxf((v[1] - mean) * rstd * g0.y + be0.y, 0.f);
    o0.z = fmaxf((v[2] - mean) * rstd * g0.z + be0.z, 0.f);
    o0.w = fmaxf((v[3] - mean) * rstd * g0.w + be0.w, 0.f);
    o1.x = fmaxf((v[4] - mean) * rstd * g1.x + be1.x, 0.f);
    o1.y = fmaxf((v[5] - mean) * rstd * g1.y + be1.y, 0.f);
    o1.z = fmaxf((v[6] - mean) * rstd * g1.z + be1.z, 0.f);
    o1.w = fmaxf((v[7] - mean) * rstd * g1.w + be1.w, 0.f);
    *(float4*)(o + l * 4) = o0;
    *(float4*)(o + 128 + l * 4) = o1;
}

// ---------------- layer-2: aggregate + den into out ----------------
__global__ void k_agg2(const float* __restrict__ xs, float* __restrict__ out) {
    int w = (blockIdx.x * blockDim.x + threadIdx.x) >> 5;
    int l = threadIdx.x & 31;
    if (w >= NN) return;
    int rs = g_rowptr[w], re = g_rowptr[w + 1];
    if (rs == re) return;
    int hsel = l >> 4;
    float4 m0 = make_float4(0.f, 0.f, 0.f, 0.f);
    float4 m1 = make_float4(0.f, 0.f, 0.f, 0.f);
    float den0 = 0.f, den1 = 0.f;
    for (int p = rs; p < re; p++) {
        int s = g_csrc[p];
        float4 al = *(const float4*)(g_alpha + (size_t)p * 4);
        const float* xr = xs + (size_t)s * D1;
        float a0 = hsel ? al.y : al.x;
        float a1 = hsel ? al.w : al.z;
        den0 += a0; den1 += a1;
        float4 v0 = *(const float4*)(xr + l * 4);
        float4 v1 = *(const float4*)(xr + 128 + l * 4);
        m0.x = fmaf(a0, v0.x, m0.x); m0.y = fmaf(a0, v0.y, m0.y);
        m0.z = fmaf(a0, v0.z, m0.z); m0.w = fmaf(a0, v0.w, m0.w);
        m1.x = fmaf(a1, v1.x, m1.x); m1.y = fmaf(a1, v1.y, m1.y);
        m1.z = fmaf(a1, v1.z, m1.z); m1.w = fmaf(a1, v1.w, m1.w);
    }
    float i0 = 1.f / (den0 + 1e-16f);
    float i1 = 1.f / (den1 + 1e-16f);
    float* o = out + (size_t)w * D1;
    float4 t0 = *(const float4*)(o + l * 4);
    float4 t1 = *(const float4*)(o + 128 + l * 4);
    t0.x = fmaf(m0.x, i0, t0.x); t0.y = fmaf(m0.y, i0, t0.y);
    t0.z = fmaf(m0.z, i0, t0.z); t0.w = fmaf(m0.w, i0, t0.w);
    t1.x = fmaf(m1.x, i1, t1.x); t1.y = fmaf(m1.y, i1, t1.y);
    t1.z = fmaf(m1.z, i1, t1.z); t1.w = fmaf(m1.w, i1, t1.w);
    *(float4*)(o + l * 4) = t0;
    *(float4*)(o + 128 + l * 4) = t1;
}

// ---------------- host launch ----------------
extern "C" void kernel_launch(void* const* d_in, const int* in_sizes, int n_in,
                              void* d_out, int out_size) {
    const float* x     = (const float*)d_in[0];
    const int*   ei    = (const int*)d_in[1];
    const float* Wsrc1 = (const float*)d_in[2];
    const float* Wdst1 = (const float*)d_in[3];
    const float* atts1 = (const float*)d_in[4];
    const float* attd1 = (const float*)d_in[5];
    const float* b1    = (const float*)d_in[6];
    const float* Wlin1 = (const float*)d_in[7];
    const float* blin1 = (const float*)d_in[8];
    const float* gamma = (const float*)d_in[9];
    const float* beta  = (const float*)d_in[10];
    const float* Wsrc2 = (const float*)d_in[11];
    const float* Wdst2 = (const float*)d_in[12];
    const float* atts2 = (const float*)d_in[13];
    const float* attd2 = (const float*)d_in[14];
    const float* b2    = (const float*)d_in[15];
    const float* Wlin2 = (const float*)d_in[16];
    const float* blin2 = (const float*)d_in[17];
    float* out = (float*)d_out;

    const int* src = ei;
    const int* dst = ei + EE;

    float *xs_p, *acc_p, *h_p;
    cudaGetSymbolAddress((void**)&xs_p, g_xs);
    cudaGetSymbolAddress((void**)&acc_p, g_acc);
    cudaGetSymbolAddress((void**)&h_p, g_h);

    // CSR (graph identical across layers)
    k_zero_deg<<<(NN + 255) / 256, 256>>>();
    k_count<<<(EE + 255) / 256, 256>>>(dst);
    k_scan<<<1, 1024>>>();
    k_fill<<<(EE + 255) / 256, 256>>>(dst, src);

    dim3 gg((NN + 127) / 128, D1 / 64);

    // ---- layer 1 (K = 128) ----
    k_vcat<<<(DIN * 8 + 255) / 256, 256>>>(Wsrc1, Wdst1, atts1, attd1, DIN);
    k_dualgemm<DIN><<<gg, 256>>>(x, Wsrc1, Wlin1, blin1, b1, xs_p, acc_p);
    k_asad<DIN><<<(NN * 32 + 255) / 256, 256>>>(x);
    k_edge_ex<<<(EE + 255) / 256, 256>>>(src, dst);
    k_agg_ln<<<(NN + 7) / 8, 256>>>(xs_p, acc_p, h_p, gamma, beta);

    // ---- layer 2 (K = 256) ----
    k_vcat<<<(D1 * 8 + 255) / 256, 256>>>(Wsrc2, Wdst2, atts2, attd2, D1);
    k_dualgemm<D1><<<gg, 256>>>(h_p, Wsrc2, Wlin2, blin2, b2, xs_p, out);
    k_asad<D1><<<(NN * 32 + 255) / 256, 256>>>(h_p);
    k_edge_ex<<<(EE + 255) / 256, 256>>>(src, dst);
    k_agg2<<<(NN + 7) / 8, 256>>>(xs_p, out);
}

// round 6
// speedup vs baseline: 2.2602x; 1.2362x over previous
#include <cuda_runtime.h>
#include <cuda_bf16.h>
#include <cuda_fp16.h>
#include <cstdint>

#define NN   50000
#define EE   800000
#define HH   4
#define CC   64
#define DIN  128
#define D1   256

// ---------------- device scratch ----------------
__device__ __half g_xs[NN * D1];        // fp16 messages (xs = X @ Wsrc)
__device__ float g_acc[NN * D1];
__device__ float g_h[NN * D1];
__device__ float g_asad[NN * 8];        // per node: a_s[0..3], a_d[0..3]
__device__ float g_alpha[EE * HH];      // CSR-ordered exp(e)
__device__ float g_vcat[D1 * 8];
__device__ int   g_deg[NN];
__device__ int   g_rowptr[NN + 1];
__device__ int   g_cursor[NN];
__device__ int   g_pos[EE];             // eid -> CSR position
__device__ int   g_csrc[EE];            // CSR position -> src node

// ---------------- CSR build ----------------
__global__ void k_zero_deg() {
    int t = blockIdx.x * blockDim.x + threadIdx.x;
    if (t < NN) g_deg[t] = 0;
}

__global__ void k_count(const int* __restrict__ dst) {
    int t = blockIdx.x * blockDim.x + threadIdx.x;
    if (t < EE) atomicAdd(&g_deg[dst[t]], 1);
}

__global__ void k_scan() {
    __shared__ int sums[1024];
    int t = threadIdx.x;
    const int CH = (NN + 1023) / 1024;
    int base = t * CH;
    int s = 0;
    for (int i = 0; i < CH; i++) {
        int idx = base + i;
        if (idx < NN) s += g_deg[idx];
    }
    int my = s;
    sums[t] = s;
    __syncthreads();
    for (int d = 1; d < 1024; d <<= 1) {
        int v = (t >= d) ? sums[t - d] : 0;
        __syncthreads();
        sums[t] += v;
        __syncthreads();
    }
    if (t == 1023) g_rowptr[NN] = sums[1023];
    int off = sums[t] - my;
    for (int i = 0; i < CH; i++) {
        int idx = base + i;
        if (idx < NN) {
            g_rowptr[idx] = off;
            g_cursor[idx] = off;
            off += g_deg[idx];
        }
    }
}

__global__ void k_fill(const int* __restrict__ dst, const int* __restrict__ src) {
    int t = blockIdx.x * blockDim.x + threadIdx.x;
    if (t < EE) {
        int d = dst[t];
        int p = atomicAdd(&g_cursor[d], 1);
        g_pos[t] = p;
        g_csrc[p] = src[t];
    }
}

// ---------------- fold att vectors ----------------
__global__ void k_vcat(const float* __restrict__ Wsrc, const float* __restrict__ Wdst,
                       const float* __restrict__ atts, const float* __restrict__ attd, int K) {
    int t = blockIdx.x * blockDim.x + threadIdx.x;
    if (t >= K * 8) return;
    int k = t >> 3, j = t & 7;
    const float* W   = (j < 4) ? Wsrc : Wdst;
    const float* att = (j < 4) ? atts : attd;
    int h = j & 3;
    float s = 0.f;
    for (int c = 0; c < CC; c++) s = fmaf(W[k * D1 + h * CC + c], att[h * CC + c], s);
    g_vcat[t] = s;
}

// ---------------- fp16 MMA helper ----------------
__device__ __forceinline__ void mma_f16(float* d, const uint32_t* a, const uint32_t* b) {
    asm volatile(
        "mma.sync.aligned.m16n8k16.row.col.f32.f16.f16.f32 "
        "{%0,%1,%2,%3}, {%4,%5,%6,%7}, {%8,%9}, {%0,%1,%2,%3};"
        : "+f"(d[0]), "+f"(d[1]), "+f"(d[2]), "+f"(d[3])
        : "r"(a[0]), "r"(a[1]), "r"(a[2]), "r"(a[3]), "r"(b[0]), "r"(b[1]));
}

__device__ __forceinline__ uint32_t pack_half2(float x, float y) {
    __half2 t = __floats2half2_rn(x, y);
    return *(uint32_t*)&t;
}

// ---------------- fused dual GEMM, fp16 inputs, f32 accum (BM=128,BN=64,BK=32) ----------------
// Y1 = X @ W1   -> half output (messages)
// Y2 = X @ W2 + b2a + b2b -> float output (skip)
template <int K>
__global__ void __launch_bounds__(256)
k_dualgemm(const float* __restrict__ X,
           const float* __restrict__ W1, const float* __restrict__ W2,
           const float* __restrict__ b2a, const float* __restrict__ b2b,
           __half* __restrict__ Y1, float* __restrict__ Y2) {
    // As: [m][k] halves, row stride 40 halves (20 words) -> conflict-free frags
    __shared__ __align__(16) uint32_t As[2][128][20];
    // Bs: k-pair interleaved [k/2][n] half2 words, row stride 72 words -> 1 LDS per frag reg
    __shared__ __align__(16) uint32_t Bs1[2][16][72];
    __shared__ __align__(16) uint32_t Bs2[2][16][72];

    const int tid = threadIdx.x;
    const int bm = blockIdx.x * 128, bn = blockIdx.y * 64;
    const int lane = tid & 31, wid = tid >> 5;
    const int wm = wid >> 1, wn = wid & 1;
    const int gid = lane >> 2, tig = lane & 3;

    const int arow = tid >> 3, aseg = tid & 7;   // A: 1024 float4 per tile, 4 iters
    const int bkr = tid >> 4, bseg = tid & 15;   // B: 512 float4 per matrix, 2 iters

    float4 ra[4], rb1[2], rb2[2];
    float acc[2][2][4][4];
#pragma unroll
    for (int m = 0; m < 2; m++)
#pragma unroll
        for (int i = 0; i < 2; i++)
#pragma unroll
            for (int j = 0; j < 4; j++)
#pragma unroll
                for (int q = 0; q < 4; q++) acc[m][i][j][q] = 0.f;

    const int KT = K / 32;

    // ---- loads for tile kt into registers ----
    auto load_tile = [&](int k0) {
#pragma unroll
        for (int i = 0; i < 4; i++) {
            int f = tid + i * 256;
            int row = f >> 3, seg = f & 7;
            int gr = bm + row;
            float4 v = make_float4(0.f, 0.f, 0.f, 0.f);
            if (gr < NN) v = *(const float4*)(X + (size_t)gr * K + k0 + seg * 4);
            ra[i] = v;
        }
#pragma unroll
        for (int i = 0; i < 2; i++) {
            int f = tid + i * 256;
            int br = f >> 4, bs = f & 15;
            rb1[i] = *(const float4*)(W1 + (size_t)(k0 + br) * D1 + bn + bs * 4);
            rb2[i] = *(const float4*)(W2 + (size_t)(k0 + br) * D1 + bn + bs * 4);
        }
    };

    auto store_tile = [&](int st) {
#pragma unroll
        for (int i = 0; i < 4; i++) {
            int f = tid + i * 256;
            int row = f >> 3, seg = f & 7;
            uint2 h;
            h.x = pack_half2(ra[i].x, ra[i].y);
            h.y = pack_half2(ra[i].z, ra[i].w);
            *(uint2*)&As[st][row][seg * 2] = h;
        }
#pragma unroll
        for (int i = 0; i < 2; i++) {
            int f = tid + i * 256;
            int br = f >> 4, bs = f & 15;
            int kp = br >> 1, hi = br & 1;
            __half* p1 = (__half*)&Bs1[st][kp][0];
            __half* p2 = (__half*)&Bs2[st][kp][0];
            float v1[4] = {rb1[i].x, rb1[i].y, rb1[i].z, rb1[i].w};
            float v2[4] = {rb2[i].x, rb2[i].y, rb2[i].z, rb2[i].w};
#pragma unroll
            for (int j = 0; j < 4; j++) {
                p1[(bs * 4 + j) * 2 + hi] = __float2half(v1[j]);
                p2[(bs * 4 + j) * 2 + hi] = __float2half(v2[j]);
            }
        }
    };

    load_tile(0);
    store_tile(0);
    __syncthreads();

    for (int kt = 0; kt < KT; kt++) {
        const int cur = kt & 1;
        const int nxt = cur ^ 1;
        if (kt + 1 < KT) load_tile((kt + 1) * 32);

#pragma unroll
        for (int ks = 0; ks < 2; ks++) {   // two k16 steps per BK=32
            uint32_t a[2][4], bf1[4][2], bf2[4][2];
#pragma unroll
            for (int mt = 0; mt < 2; mt++) {
                int mr = wm * 32 + mt * 16 + gid;
                int kw = ks * 8 + tig;       // word index of k-pair
                a[mt][0] = As[cur][mr][kw];
                a[mt][1] = As[cur][mr + 8][kw];
                a[mt][2] = As[cur][mr][kw + 4];
                a[mt][3] = As[cur][mr + 8][kw + 4];
            }
#pragma unroll
            for (int nt = 0; nt < 4; nt++) {
                int nc = wn * 32 + nt * 8 + gid;
                int kp = ks * 8 + tig;
                bf1[nt][0] = Bs1[cur][kp][nc];
                bf1[nt][1] = Bs1[cur][kp + 4][nc];
                bf2[nt][0] = Bs2[cur][kp][nc];
                bf2[nt][1] = Bs2[cur][kp + 4][nc];
            }
#pragma unroll
            for (int mt = 0; mt < 2; mt++)
#pragma unroll
                for (int nt = 0; nt < 4; nt++) {
                    mma_f16(acc[0][mt][nt], a[mt], bf1[nt]);
                    mma_f16(acc[1][mt][nt], a[mt], bf2[nt]);
                }
        }

        if (kt + 1 < KT) store_tile(nxt);
        __syncthreads();
    }

    // epilogue: Y1 half, Y2 float(+biases)
#pragma unroll
    for (int mt = 0; mt < 2; mt++) {
#pragma unroll
        for (int nt = 0; nt < 4; nt++) {
            int r0 = bm + wm * 32 + mt * 16 + gid;
            int c0 = bn + wn * 32 + nt * 8 + tig * 2;
            float bb0 = b2a[c0] + b2b[c0];
            float bb1 = b2a[c0 + 1] + b2b[c0 + 1];
            if (r0 < NN) {
                __half2 h = __floats2half2_rn(acc[0][mt][nt][0], acc[0][mt][nt][1]);
                *(__half2*)(Y1 + (size_t)r0 * D1 + c0) = h;
                *(float2*)(Y2 + (size_t)r0 * D1 + c0) =
                    make_float2(acc[1][mt][nt][0] + bb0, acc[1][mt][nt][1] + bb1);
            }
            if (r0 + 8 < NN) {
                __half2 h = __floats2half2_rn(acc[0][mt][nt][2], acc[0][mt][nt][3]);
                *(__half2*)(Y1 + (size_t)(r0 + 8) * D1 + c0) = h;
                *(float2*)(Y2 + (size_t)(r0 + 8) * D1 + c0) =
                    make_float2(acc[1][mt][nt][2] + bb0, acc[1][mt][nt][3] + bb1);
            }
        }
    }
}

// ---------------- a_s/a_d: warp per node ----------------
template <int K>
__global__ void k_asad(const float* __restrict__ X) {
    int w = (blockIdx.x * blockDim.x + threadIdx.x) >> 5;
    int l = threadIdx.x & 31;
    if (w >= NN) return;
    const float* xr = X + (size_t)w * K;
    float s[8] = {0.f, 0.f, 0.f, 0.f, 0.f, 0.f, 0.f, 0.f};
#pragma unroll
    for (int q = 0; q < K / 32; q++) {
        int k = l + 32 * q;
        float xv = xr[k];
        float4 v0 = *(const float4*)&g_vcat[k * 8];
        float4 v1 = *(const float4*)&g_vcat[k * 8 + 4];
        s[0] = fmaf(xv, v0.x, s[0]); s[1] = fmaf(xv, v0.y, s[1]);
        s[2] = fmaf(xv, v0.z, s[2]); s[3] = fmaf(xv, v0.w, s[3]);
        s[4] = fmaf(xv, v1.x, s[4]); s[5] = fmaf(xv, v1.y, s[5]);
        s[6] = fmaf(xv, v1.z, s[6]); s[7] = fmaf(xv, v1.w, s[7]);
    }
#pragma unroll
    for (int j = 0; j < 8; j++) {
#pragma unroll
        for (int d = 16; d > 0; d >>= 1) s[j] += __shfl_xor_sync(0xFFFFFFFFu, s[j], d);
    }
    if (l < 8) g_asad[w * 8 + l] = s[l];
}

// ---------------- edge-parallel exp(leaky(a_s+a_d)), CSR order ----------------
__global__ void k_edge_ex(const int* __restrict__ src, const int* __restrict__ dst) {
    int t = blockIdx.x * blockDim.x + threadIdx.x;
    if (t >= EE) return;
    int s = src[t], d = dst[t];
    float4 as = *(const float4*)&g_asad[s * 8];
    float4 ad = *(const float4*)&g_asad[d * 8 + 4];
    float4 e;
    e.x = as.x + ad.x; e.y = as.y + ad.y; e.z = as.z + ad.z; e.w = as.w + ad.w;
    e.x = (e.x > 0.f) ? e.x : 0.2f * e.x;
    e.y = (e.y > 0.f) ? e.y : 0.2f * e.y;
    e.z = (e.z > 0.f) ? e.z : 0.2f * e.z;
    e.w = (e.w > 0.f) ? e.w : 0.2f * e.w;
    e.x = __expf(e.x); e.y = __expf(e.y); e.z = __expf(e.z); e.w = __expf(e.w);
    *(float4*)&g_alpha[(size_t)g_pos[t] * 4] = e;
}

// ---------------- aggregation core: lane covers 8 consecutive cols ----------------
__device__ __forceinline__ void agg_row(int w, int l, const __half* __restrict__ xs,
                                        float* acc, float& inv) {
    int rs = g_rowptr[w], re = g_rowptr[w + 1];
    int head = l >> 3;
    float den = 0.f;
    for (int p = rs; p < re; p++) {
        int s = g_csrc[p];
        float a = g_alpha[(size_t)p * 4 + head];
        den += a;
        uint4 v = *(const uint4*)(xs + (size_t)s * D1 + l * 8);
        const __half2* hp = (const __half2*)&v;
        float2 f0 = __half22float2(hp[0]);
        float2 f1 = __half22float2(hp[1]);
        float2 f2 = __half22float2(hp[2]);
        float2 f3 = __half22float2(hp[3]);
        acc[0] = fmaf(a, f0.x, acc[0]); acc[1] = fmaf(a, f0.y, acc[1]);
        acc[2] = fmaf(a, f1.x, acc[2]); acc[3] = fmaf(a, f1.y, acc[3]);
        acc[4] = fmaf(a, f2.x, acc[4]); acc[5] = fmaf(a, f2.y, acc[5]);
        acc[6] = fmaf(a, f3.x, acc[6]); acc[7] = fmaf(a, f3.y, acc[7]);
    }
    inv = 1.f / (den + 1e-16f);
}

// ---------------- layer-1: aggregate + skip + LayerNorm + ReLU (warp/node) ----------------
__global__ void k_agg_ln(const __half* __restrict__ xs, const float* __restrict__ skip,
                         float* __restrict__ hout,
                         const float* __restrict__ gamma, const float* __restrict__ beta) {
    int w = (blockIdx.x * blockDim.x + threadIdx.x) >> 5;
    int l = threadIdx.x & 31;
    if (w >= NN) return;
    float m[8] = {0.f, 0.f, 0.f, 0.f, 0.f, 0.f, 0.f, 0.f};
    float inv;
    agg_row(w, l, xs, m, inv);

    const float* sk = skip + (size_t)w * D1 + l * 8;
    float4 s0 = *(const float4*)(sk);
    float4 s1 = *(const float4*)(sk + 4);
    float v[8] = {s0.x + m[0] * inv, s0.y + m[1] * inv, s0.z + m[2] * inv, s0.w + m[3] * inv,
                  s1.x + m[4] * inv, s1.y + m[5] * inv, s1.z + m[6] * inv, s1.w + m[7] * inv};
    float sm = 0.f, sq = 0.f;
#pragma unroll
    for (int k = 0; k < 8; k++) { sm += v[k]; sq += v[k] * v[k]; }
#pragma unroll
    for (int d = 16; d > 0; d >>= 1) {
        sm += __shfl_xor_sync(0xFFFFFFFFu, sm, d);
        sq += __shfl_xor_sync(0xFFFFFFFFu, sq, d);
    }
    float mean = sm * (1.f / D1);
    float var = sq * (1.f / D1) - mean * mean;
    float rstd = rsqrtf(var + 1e-5f);
    const float* gp = gamma + l * 8;
    const float* bp = beta + l * 8;
    float4 g0 = *(const float4*)(gp);
    float4 g1 = *(const float4*)(gp + 4);
    float4 be0 = *(const float4*)(bp);
    float4 be1 = *(const float4*)(bp + 4);
    float* o = hout + (size_t)w * D1 + l * 8;
    float4 o0, o1;
    o0.x = fmaxf((v[0] - mean) * rstd * g0.x + be0.x, 0.f);
    o0.y = fmaxf((v[1] - mean) * rstd * g0.y + be0.y, 0.f);
    o0.z = fmaxf((v[2] - mean) * rstd * g0.z + be0.z, 0.f);
    o0.w = fmaxf((v[3] - mean) * rstd * g0.w + be0.w, 0.f);
    o1.x = fmaxf((v[4] - mean) * rstd * g1.x + be1.x, 0.f);
    o1.y = fmaxf((v[5] - mean) * rstd * g1.y + be1.y, 0.f);
    o1.z = fmaxf((v[6] - mean) * rstd * g1.z + be1.z, 0.f);
    o1.w = fmaxf((v[7] - mean) * rstd * g1.w + be1.w, 0.f);
    *(float4*)(o) = o0;
    *(float4*)(o + 4) = o1;
}

// ---------------- layer-2: aggregate into out ----------------
__global__ void k_agg2(const __half* __restrict__ xs, float* __restrict__ out) {
    int w = (blockIdx.x * blockDim.x + threadIdx.x) >> 5;
    int l = threadIdx.x & 31;
    if (w >= NN) return;
    int rs = g_rowptr[w], re = g_rowptr[w + 1];
    if (rs == re) return;
    float m[8] = {0.f, 0.f, 0.f, 0.f, 0.f, 0.f, 0.f, 0.f};
    float inv;
    agg_row(w, l, xs, m, inv);
    float* o = out + (size_t)w * D1 + l * 8;
    float4 t0 = *(const float4*)(o);
    float4 t1 = *(const float4*)(o + 4);
    t0.x = fmaf(m[0], inv, t0.x); t0.y = fmaf(m[1], inv, t0.y);
    t0.z = fmaf(m[2], inv, t0.z); t0.w = fmaf(m[3], inv, t0.w);
    t1.x = fmaf(m[4], inv, t1.x); t1.y = fmaf(m[5], inv, t1.y);
    t1.z = fmaf(m[6], inv, t1.z); t1.w = fmaf(m[7], inv, t1.w);
    *(float4*)(o) = t0;
    *(float4*)(o + 4) = t1;
}

// ---------------- host launch ----------------
extern "C" void kernel_launch(void* const* d_in, const int* in_sizes, int n_in,
                              void* d_out, int out_size) {
    const float* x     = (const float*)d_in[0];
    const int*   ei    = (const int*)d_in[1];
    const float* Wsrc1 = (const float*)d_in[2];
    const float* Wdst1 = (const float*)d_in[3];
    const float* atts1 = (const float*)d_in[4];
    const float* attd1 = (const float*)d_in[5];
    const float* b1    = (const float*)d_in[6];
    const float* Wlin1 = (const float*)d_in[7];
    const float* blin1 = (const float*)d_in[8];
    const float* gamma = (const float*)d_in[9];
    const float* beta  = (const float*)d_in[10];
    const float* Wsrc2 = (const float*)d_in[11];
    const float* Wdst2 = (const float*)d_in[12];
    const float* atts2 = (const float*)d_in[13];
    const float* attd2 = (const float*)d_in[14];
    const float* b2    = (const float*)d_in[15];
    const float* Wlin2 = (const float*)d_in[16];
    const float* blin2 = (const float*)d_in[17];
    float* out = (float*)d_out;

    const int* src = ei;
    const int* dst = ei + EE;

    __half* xs_p;
    float *acc_p, *h_p;
    cudaGetSymbolAddress((void**)&xs_p, g_xs);
    cudaGetSymbolAddress((void**)&acc_p, g_acc);
    cudaGetSymbolAddress((void**)&h_p, g_h);

    // CSR (graph identical across layers)
    k_zero_deg<<<(NN + 255) / 256, 256>>>();
    k_count<<<(EE + 255) / 256, 256>>>(dst);
    k_scan<<<1, 1024>>>();
    k_fill<<<(EE + 255) / 256, 256>>>(dst, src);

    dim3 gg((NN + 127) / 128, D1 / 64);

    // ---- layer 1 (K = 128) ----
    k_vcat<<<(DIN * 8 + 255) / 256, 256>>>(Wsrc1, Wdst1, atts1, attd1, DIN);
    k_dualgemm<DIN><<<gg, 256>>>(x, Wsrc1, Wlin1, blin1, b1, xs_p, acc_p);
    k_asad<DIN><<<(NN * 32 + 255) / 256, 256>>>(x);
    k_edge_ex<<<(EE + 255) / 256, 256>>>(src, dst);
    k_agg_ln<<<(NN + 7) / 8, 256>>>(xs_p, acc_p, h_p, gamma, beta);

    // ---- layer 2 (K = 256) ----
    k_vcat<<<(D1 * 8 + 255) / 256, 256>>>(Wsrc2, Wdst2, atts2, attd2, D1);
    k_dualgemm<D1><<<gg, 256>>>(h_p, Wsrc2, Wlin2, blin2, b2, xs_p, out);
    k_asad<D1><<<(NN * 32 + 255) / 256, 256>>>(h_p);
    k_edge_ex<<<(EE + 255) / 256, 256>>>(src, dst);
    k_agg2<<<(NN + 7) / 8, 256>>>(xs_p, out);
}

// round 7
// speedup vs baseline: 2.4223x; 1.0718x over previous
#include <cuda_runtime.h>
#include <cuda_bf16.h>
#include <cuda_fp16.h>
#include <cstdint>

#define NN   50000
#define EE   800000
#define HH   4
#define CC   64
#define DIN  128
#define D1   256

// ---------------- device scratch ----------------
__device__ __half g_xs[NN * D1];        // fp16 messages (xs = X @ Wsrc)
__device__ float  g_acc[NN * D1];       // layer-1 skip accumulator (float)
__device__ __half g_hh[NN * D1];        // hidden after LN+ReLU (fp16)
__device__ float  g_asad[NN * 8];       // per node: a_s[0..3], a_d[0..3]
__device__ float  g_alpha[EE * HH];     // CSR-ordered exp(e)
__device__ float  g_vcat[D1 * 8];
__device__ int    g_deg[NN];
__device__ int    g_rowptr[NN + 1];
__device__ int    g_cursor[NN];
__device__ int    g_csrc[EE];           // CSR position -> src node
__device__ int    g_cdst[EE];           // CSR position -> dst node

// ---------------- CSR build ----------------
__global__ void k_zero_deg() {
    int t = blockIdx.x * blockDim.x + threadIdx.x;
    if (t < NN) g_deg[t] = 0;
}

__global__ void k_count(const int* __restrict__ dst) {
    int t = blockIdx.x * blockDim.x + threadIdx.x;
    if (t < EE) atomicAdd(&g_deg[dst[t]], 1);
}

__global__ void k_scan() {
    __shared__ int sums[1024];
    int t = threadIdx.x;
    const int CH = (NN + 1023) / 1024;
    int base = t * CH;
    int s = 0;
    for (int i = 0; i < CH; i++) {
        int idx = base + i;
        if (idx < NN) s += g_deg[idx];
    }
    int my = s;
    sums[t] = s;
    __syncthreads();
    for (int d = 1; d < 1024; d <<= 1) {
        int v = (t >= d) ? sums[t - d] : 0;
        __syncthreads();
        sums[t] += v;
        __syncthreads();
    }
    if (t == 1023) g_rowptr[NN] = sums[1023];
    int off = sums[t] - my;
    for (int i = 0; i < CH; i++) {
        int idx = base + i;
        if (idx < NN) {
            g_rowptr[idx] = off;
            g_cursor[idx] = off;
            off += g_deg[idx];
        }
    }
}

__global__ void k_fill(const int* __restrict__ dst, const int* __restrict__ src) {
    int t = blockIdx.x * blockDim.x + threadIdx.x;
    if (t < EE) {
        int d = dst[t];
        int p = atomicAdd(&g_cursor[d], 1);
        g_csrc[p] = src[t];
        g_cdst[p] = d;
    }
}

// ---------------- fold att vectors ----------------
__global__ void k_vcat(const float* __restrict__ Wsrc, const float* __restrict__ Wdst,
                       const float* __restrict__ atts, const float* __restrict__ attd, int K) {
    int t = blockIdx.x * blockDim.x + threadIdx.x;
    if (t >= K * 8) return;
    int k = t >> 3, j = t & 7;
    const float* W   = (j < 4) ? Wsrc : Wdst;
    const float* att = (j < 4) ? atts : attd;
    int h = j & 3;
    float s = 0.f;
    for (int c = 0; c < CC; c++) s = fmaf(W[k * D1 + h * CC + c], att[h * CC + c], s);
    g_vcat[t] = s;
}

// ---------------- fp16 MMA helper ----------------
__device__ __forceinline__ void mma_f16(float* d, const uint32_t* a, const uint32_t* b) {
    asm volatile(
        "mma.sync.aligned.m16n8k16.row.col.f32.f16.f16.f32 "
        "{%0,%1,%2,%3}, {%4,%5,%6,%7}, {%8,%9}, {%0,%1,%2,%3};"
        : "+f"(d[0]), "+f"(d[1]), "+f"(d[2]), "+f"(d[3])
        : "r"(a[0]), "r"(a[1]), "r"(a[2]), "r"(a[3]), "r"(b[0]), "r"(b[1]));
}

__device__ __forceinline__ uint32_t pack_half2(float x, float y) {
    __half2 t = __floats2half2_rn(x, y);
    return *(uint32_t*)&t;
}

// ---------------- fused dual GEMM, fp16 inputs, f32 accum (BM=128,BN=64,BK=32) ----------------
// Y1 = X @ W1   -> half output (messages)
// Y2 = X @ W2 + b2a + b2b -> float output (skip)
template <int K, typename TA>
__global__ void __launch_bounds__(256)
k_dualgemm(const TA* __restrict__ X,
           const float* __restrict__ W1, const float* __restrict__ W2,
           const float* __restrict__ b2a, const float* __restrict__ b2b,
           __half* __restrict__ Y1, float* __restrict__ Y2) {
    // As: [m][k] halves, row stride 20 words -> conflict-free frags
    __shared__ __align__(16) uint32_t As[2][128][20];
    // Bs: k-pair interleaved [k/2][n] half2 words, row stride 72 words
    __shared__ __align__(16) uint32_t Bs1[2][16][72];
    __shared__ __align__(16) uint32_t Bs2[2][16][72];

    const int tid = threadIdx.x;
    const int bm = blockIdx.x * 128, bn = blockIdx.y * 64;
    const int lane = tid & 31, wid = tid >> 5;
    const int wm = wid >> 1, wn = wid & 1;
    const int gid = lane >> 2, tig = lane & 3;

    // B loader indices: thread owns k-pair kp, 4 columns at nq*4
    const int kp = tid >> 4, nq = tid & 15;

    float4 raf[4];        // fp32 A path
    uint4  rah[2];        // fp16 A path
    float4 rb1a, rb1b, rb2a, rb2b;

    float acc[2][2][4][4];
#pragma unroll
    for (int m = 0; m < 2; m++)
#pragma unroll
        for (int i = 0; i < 2; i++)
#pragma unroll
            for (int j = 0; j < 4; j++)
#pragma unroll
                for (int q = 0; q < 4; q++) acc[m][i][j][q] = 0.f;

    const int KT = K / 32;

    auto load_tile = [&](int k0) {
        if constexpr (sizeof(TA) == 4) {
#pragma unroll
            for (int i = 0; i < 4; i++) {
                int f = tid + i * 256;
                int row = f >> 3, seg = f & 7;
                int gr = bm + row;
                float4 v = make_float4(0.f, 0.f, 0.f, 0.f);
                if (gr < NN) v = *(const float4*)((const float*)X + (size_t)gr * K + k0 + seg * 4);
                raf[i] = v;
            }
        } else {
#pragma unroll
            for (int i = 0; i < 2; i++) {
                int f = tid + i * 256;
                int row = f >> 2, sq = f & 3;
                int gr = bm + row;
                uint4 v = make_uint4(0u, 0u, 0u, 0u);
                if (gr < NN) v = *(const uint4*)((const __half*)X + (size_t)gr * K + k0 + sq * 8);
                rah[i] = v;
            }
        }
        rb1a = *(const float4*)(W1 + (size_t)(k0 + 2 * kp) * D1 + bn + nq * 4);
        rb1b = *(const float4*)(W1 + (size_t)(k0 + 2 * kp + 1) * D1 + bn + nq * 4);
        rb2a = *(const float4*)(W2 + (size_t)(k0 + 2 * kp) * D1 + bn + nq * 4);
        rb2b = *(const float4*)(W2 + (size_t)(k0 + 2 * kp + 1) * D1 + bn + nq * 4);
    };

    auto store_tile = [&](int st) {
        if constexpr (sizeof(TA) == 4) {
#pragma unroll
            for (int i = 0; i < 4; i++) {
                int f = tid + i * 256;
                int row = f >> 3, seg = f & 7;
                uint2 h;
                h.x = pack_half2(raf[i].x, raf[i].y);
                h.y = pack_half2(raf[i].z, raf[i].w);
                *(uint2*)&As[st][row][seg * 2] = h;
            }
        } else {
#pragma unroll
            for (int i = 0; i < 2; i++) {
                int f = tid + i * 256;
                int row = f >> 2, sq = f & 3;
                *(uint4*)&As[st][row][sq * 4] = rah[i];
            }
        }
        uint4 w;
        w.x = pack_half2(rb1a.x, rb1b.x);
        w.y = pack_half2(rb1a.y, rb1b.y);
        w.z = pack_half2(rb1a.z, rb1b.z);
        w.w = pack_half2(rb1a.w, rb1b.w);
        *(uint4*)&Bs1[st][kp][nq * 4] = w;
        w.x = pack_half2(rb2a.x, rb2b.x);
        w.y = pack_half2(rb2a.y, rb2b.y);
        w.z = pack_half2(rb2a.z, rb2b.z);
        w.w = pack_half2(rb2a.w, rb2b.w);
        *(uint4*)&Bs2[st][kp][nq * 4] = w;
    };

    load_tile(0);
    store_tile(0);
    __syncthreads();

    for (int kt = 0; kt < KT; kt++) {
        const int cur = kt & 1;
        const int nxt = cur ^ 1;
        if (kt + 1 < KT) load_tile((kt + 1) * 32);

#pragma unroll
        for (int ks = 0; ks < 2; ks++) {
            uint32_t a[2][4], bf1[4][2], bf2[4][2];
#pragma unroll
            for (int mt = 0; mt < 2; mt++) {
                int mr = wm * 32 + mt * 16 + gid;
                int kw = ks * 8 + tig;
                a[mt][0] = As[cur][mr][kw];
                a[mt][1] = As[cur][mr + 8][kw];
                a[mt][2] = As[cur][mr][kw + 4];
                a[mt][3] = As[cur][mr + 8][kw + 4];
            }
#pragma unroll
            for (int nt = 0; nt < 4; nt++) {
                int nc = wn * 32 + nt * 8 + gid;
                int kq = ks * 8 + tig;
                bf1[nt][0] = Bs1[cur][kq][nc];
                bf1[nt][1] = Bs1[cur][kq + 4][nc];
                bf2[nt][0] = Bs2[cur][kq][nc];
                bf2[nt][1] = Bs2[cur][kq + 4][nc];
            }
#pragma unroll
            for (int mt = 0; mt < 2; mt++)
#pragma unroll
                for (int nt = 0; nt < 4; nt++) {
                    mma_f16(acc[0][mt][nt], a[mt], bf1[nt]);
                    mma_f16(acc[1][mt][nt], a[mt], bf2[nt]);
                }
        }

        if (kt + 1 < KT) store_tile(nxt);
        __syncthreads();
    }

    // epilogue: Y1 half, Y2 float(+biases)
#pragma unroll
    for (int mt = 0; mt < 2; mt++) {
#pragma unroll
        for (int nt = 0; nt < 4; nt++) {
            int r0 = bm + wm * 32 + mt * 16 + gid;
            int c0 = bn + wn * 32 + nt * 8 + tig * 2;
            float bb0 = b2a[c0] + b2b[c0];
            float bb1 = b2a[c0 + 1] + b2b[c0 + 1];
            if (r0 < NN) {
                __half2 h = __floats2half2_rn(acc[0][mt][nt][0], acc[0][mt][nt][1]);
                *(__half2*)(Y1 + (size_t)r0 * D1 + c0) = h;
                *(float2*)(Y2 + (size_t)r0 * D1 + c0) =
                    make_float2(acc[1][mt][nt][0] + bb0, acc[1][mt][nt][1] + bb1);
            }
            if (r0 + 8 < NN) {
                __half2 h = __floats2half2_rn(acc[0][mt][nt][2], acc[0][mt][nt][3]);
                *(__half2*)(Y1 + (size_t)(r0 + 8) * D1 + c0) = h;
                *(float2*)(Y2 + (size_t)(r0 + 8) * D1 + c0) =
                    make_float2(acc[1][mt][nt][2] + bb0, acc[1][mt][nt][3] + bb1);
            }
        }
    }
}

// ---------------- a_s/a_d: warp per node ----------------
template <int K, typename TA>
__global__ void k_asad(const TA* __restrict__ X) {
    int w = (blockIdx.x * blockDim.x + threadIdx.x) >> 5;
    int l = threadIdx.x & 31;
    if (w >= NN) return;
    const TA* xr = X + (size_t)w * K;
    float s[8] = {0.f, 0.f, 0.f, 0.f, 0.f, 0.f, 0.f, 0.f};
#pragma unroll
    for (int q = 0; q < K / 32; q++) {
        int k = l + 32 * q;
        float xv;
        if constexpr (sizeof(TA) == 4) xv = (float)xr[k];
        else                           xv = __half2float(xr[k]);
        float4 v0 = *(const float4*)&g_vcat[k * 8];
        float4 v1 = *(const float4*)&g_vcat[k * 8 + 4];
        s[0] = fmaf(xv, v0.x, s[0]); s[1] = fmaf(xv, v0.y, s[1]);
        s[2] = fmaf(xv, v0.z, s[2]); s[3] = fmaf(xv, v0.w, s[3]);
        s[4] = fmaf(xv, v1.x, s[4]); s[5] = fmaf(xv, v1.y, s[5]);
        s[6] = fmaf(xv, v1.z, s[6]); s[7] = fmaf(xv, v1.w, s[7]);
    }
#pragma unroll
    for (int j = 0; j < 8; j++) {
#pragma unroll
        for (int d = 16; d > 0; d >>= 1) s[j] += __shfl_xor_sync(0xFFFFFFFFu, s[j], d);
    }
    if (l < 8) g_asad[w * 8 + l] = s[l];
}

// ---------------- CSR-position-parallel exp(leaky(a_s+a_d)) ----------------
// Softmax is shift invariant; scores here are O(1) so exp cannot overflow.
__global__ void k_edge_ex() {
    int p = blockIdx.x * blockDim.x + threadIdx.x;
    if (p >= EE) return;
    int s = g_csrc[p], d = g_cdst[p];
    float4 as = *(const float4*)&g_asad[s * 8];
    float4 ad = *(const float4*)&g_asad[d * 8 + 4];
    float4 e;
    e.x = as.x + ad.x; e.y = as.y + ad.y; e.z = as.z + ad.z; e.w = as.w + ad.w;
    e.x = (e.x > 0.f) ? e.x : 0.2f * e.x;
    e.y = (e.y > 0.f) ? e.y : 0.2f * e.y;
    e.z = (e.z > 0.f) ? e.z : 0.2f * e.z;
    e.w = (e.w > 0.f) ? e.w : 0.2f * e.w;
    e.x = __expf(e.x); e.y = __expf(e.y); e.z = __expf(e.z); e.w = __expf(e.w);
    *(float4*)&g_alpha[(size_t)p * 4] = e;
}

// ---------------- aggregation core: lane covers 8 consecutive cols ----------------
__device__ __forceinline__ void agg_row(int w, int l, const __half* __restrict__ xs,
                                        float* acc, float& inv) {
    int rs = g_rowptr[w], re = g_rowptr[w + 1];
    int head = l >> 3;
    float den = 0.f;
    int p = rs;
    for (; p + 1 < re; p += 2) {
        int s0 = g_csrc[p], s1 = g_csrc[p + 1];
        float a0 = g_alpha[(size_t)p * 4 + head];
        float a1 = g_alpha[(size_t)(p + 1) * 4 + head];
        den += a0 + a1;
        uint4 v0 = *(const uint4*)(xs + (size_t)s0 * D1 + l * 8);
        uint4 v1 = *(const uint4*)(xs + (size_t)s1 * D1 + l * 8);
        const __half2* h0 = (const __half2*)&v0;
        const __half2* h1 = (const __half2*)&v1;
#pragma unroll
        for (int j = 0; j < 4; j++) {
            float2 f0 = __half22float2(h0[j]);
            float2 f1 = __half22float2(h1[j]);
            acc[2 * j]     = fmaf(a0, f0.x, acc[2 * j]);
            acc[2 * j + 1] = fmaf(a0, f0.y, acc[2 * j + 1]);
            acc[2 * j]     = fmaf(a1, f1.x, acc[2 * j]);
            acc[2 * j + 1] = fmaf(a1, f1.y, acc[2 * j + 1]);
        }
    }
    if (p < re) {
        int s0 = g_csrc[p];
        float a0 = g_alpha[(size_t)p * 4 + head];
        den += a0;
        uint4 v0 = *(const uint4*)(xs + (size_t)s0 * D1 + l * 8);
        const __half2* h0 = (const __half2*)&v0;
#pragma unroll
        for (int j = 0; j < 4; j++) {
            float2 f0 = __half22float2(h0[j]);
            acc[2 * j]     = fmaf(a0, f0.x, acc[2 * j]);
            acc[2 * j + 1] = fmaf(a0, f0.y, acc[2 * j + 1]);
        }
    }
    inv = 1.f / (den + 1e-16f);
}

// ---------------- layer-1: aggregate + skip + LayerNorm + ReLU -> half h ----------------
__global__ void k_agg_ln(const __half* __restrict__ xs, const float* __restrict__ skip,
                         __half* __restrict__ hout,
                         const float* __restrict__ gamma, const float* __restrict__ beta) {
    int w = (blockIdx.x * blockDim.x + threadIdx.x) >> 5;
    int l = threadIdx.x & 31;
    if (w >= NN) return;
    float m[8] = {0.f, 0.f, 0.f, 0.f, 0.f, 0.f, 0.f, 0.f};
    float inv;
    agg_row(w, l, xs, m, inv);

    const float* sk = skip + (size_t)w * D1 + l * 8;
    float4 s0 = *(const float4*)(sk);
    float4 s1 = *(const float4*)(sk + 4);
    float v[8] = {s0.x + m[0] * inv, s0.y + m[1] * inv, s0.z + m[2] * inv, s0.w + m[3] * inv,
                  s1.x + m[4] * inv, s1.y + m[5] * inv, s1.z + m[6] * inv, s1.w + m[7] * inv};
    float sm = 0.f, sq = 0.f;
#pragma unroll
    for (int k = 0; k < 8; k++) { sm += v[k]; sq += v[k] * v[k]; }
#pragma unroll
    for (int d = 16; d > 0; d >>= 1) {
        sm += __shfl_xor_sync(0xFFFFFFFFu, sm, d);
        sq += __shfl_xor_sync(0xFFFFFFFFu, sq, d);
    }
    float mean = sm * (1.f / D1);
    float var = sq * (1.f / D1) - mean * mean;
    float rstd = rsqrtf(var + 1e-5f);
    const float* gp = gamma + l * 8;
    const float* bp = beta + l * 8;
    float4 g0 = *(const float4*)(gp);
    float4 g1 = *(const float4*)(gp + 4);
    float4 be0 = *(const float4*)(bp);
    float4 be1 = *(const float4*)(bp + 4);
    float r[8];
    r[0] = fmaxf((v[0] - mean) * rstd * g0.x + be0.x, 0.f);
    r[1] = fmaxf((v[1] - mean) * rstd * g0.y + be0.y, 0.f);
    r[2] = fmaxf((v[2] - mean) * rstd * g0.z + be0.z, 0.f);
    r[3] = fmaxf((v[3] - mean) * rstd * g0.w + be0.w, 0.f);
    r[4] = fmaxf((v[4] - mean) * rstd * g1.x + be1.x, 0.f);
    r[5] = fmaxf((v[5] - mean) * rstd * g1.y + be1.y, 0.f);
    r[6] = fmaxf((v[6] - mean) * rstd * g1.z + be1.z, 0.f);
    r[7] = fmaxf((v[7] - mean) * rstd * g1.w + be1.w, 0.f);
    uint4 hv;
    hv.x = pack_half2(r[0], r[1]);
    hv.y = pack_half2(r[2], r[3]);
    hv.z = pack_half2(r[4], r[5]);
    hv.w = pack_half2(r[6], r[7]);
    *(uint4*)(hout + (size_t)w * D1 + l * 8) = hv;
}

// ---------------- layer-2: aggregate into out ----------------
__global__ void k_agg2(const __half* __restrict__ xs, float* __restrict__ out) {
    int w = (blockIdx.x * blockDim.x + threadIdx.x) >> 5;
    int l = threadIdx.x & 31;
    if (w >= NN) return;
    int rs = g_rowptr[w], re = g_rowptr[w + 1];
    if (rs == re) return;
    float m[8] = {0.f, 0.f, 0.f, 0.f, 0.f, 0.f, 0.f, 0.f};
    float inv;
    agg_row(w, l, xs, m, inv);
    float* o = out + (size_t)w * D1 + l * 8;
    float4 t0 = *(const float4*)(o);
    float4 t1 = *(const float4*)(o + 4);
    t0.x = fmaf(m[0], inv, t0.x); t0.y = fmaf(m[1], inv, t0.y);
    t0.z = fmaf(m[2], inv, t0.z); t0.w = fmaf(m[3], inv, t0.w);
    t1.x = fmaf(m[4], inv, t1.x); t1.y = fmaf(m[5], inv, t1.y);
    t1.z = fmaf(m[6], inv, t1.z); t1.w = fmaf(m[7], inv, t1.w);
    *(float4*)(o) = t0;
    *(float4*)(o + 4) = t1;
}

// ---------------- host launch ----------------
extern "C" void kernel_launch(void* const* d_in, const int* in_sizes, int n_in,
                              void* d_out, int out_size) {
    const float* x     = (const float*)d_in[0];
    const int*   ei    = (const int*)d_in[1];
    const float* Wsrc1 = (const float*)d_in[2];
    const float* Wdst1 = (const float*)d_in[3];
    const float* atts1 = (const float*)d_in[4];
    const float* attd1 = (const float*)d_in[5];
    const float* b1    = (const float*)d_in[6];
    const float* Wlin1 = (const float*)d_in[7];
    const float* blin1 = (const float*)d_in[8];
    const float* gamma = (const float*)d_in[9];
    const float* beta  = (const float*)d_in[10];
    const float* Wsrc2 = (const float*)d_in[11];
    const float* Wdst2 = (const float*)d_in[12];
    const float* atts2 = (const float*)d_in[13];
    const float* attd2 = (const float*)d_in[14];
    const float* b2    = (const float*)d_in[15];
    const float* Wlin2 = (const float*)d_in[16];
    const float* blin2 = (const float*)d_in[17];
    float* out = (float*)d_out;

    const int* src = ei;
    const int* dst = ei + EE;

    __half *xs_p, *hh_p;
    float* acc_p;
    cudaGetSymbolAddress((void**)&xs_p, g_xs);
    cudaGetSymbolAddress((void**)&acc_p, g_acc);
    cudaGetSymbolAddress((void**)&hh_p, g_hh);

    // CSR (graph identical across layers)
    k_zero_deg<<<(NN + 255) / 256, 256>>>();
    k_count<<<(EE + 255) / 256, 256>>>(dst);
    k_scan<<<1, 1024>>>();
    k_fill<<<(EE + 255) / 256, 256>>>(dst, src);

    dim3 gg((NN + 127) / 128, D1 / 64);

    // ---- layer 1 (K = 128, A fp32) ----
    k_vcat<<<(DIN * 8 + 255) / 256, 256>>>(Wsrc1, Wdst1, atts1, attd1, DIN);
    k_dualgemm<DIN, float><<<gg, 256>>>(x, Wsrc1, Wlin1, blin1, b1, xs_p, acc_p);
    k_asad<DIN, float><<<(NN * 32 + 255) / 256, 256>>>(x);
    k_edge_ex<<<(EE + 255) / 256, 256>>>();
    k_agg_ln<<<(NN + 7) / 8, 256>>>(xs_p, acc_p, hh_p, gamma, beta);

    // ---- layer 2 (K = 256, A fp16) ----
    k_vcat<<<(D1 * 8 + 255) / 256, 256>>>(Wsrc2, Wdst2, atts2, attd2, D1);
    k_dualgemm<D1, __half><<<gg, 256>>>(hh_p, Wsrc2, Wlin2, blin2, b2, xs_p, out);
    k_asad<D1, __half><<<(NN * 32 + 255) / 256, 256>>>(hh_p);
    k_edge_ex<<<(EE + 255) / 256, 256>>>();
    k_agg2<<<(NN + 7) / 8, 256>>>(xs_p, out);
}

// round 8
// speedup vs baseline: 2.5154x; 1.0384x over previous
#include <cuda_runtime.h>
#include <cuda_bf16.h>
#include <cuda_fp16.h>
#include <cstdint>

#define NN   50000
#define EE   800000
#define HH   4
#define CC   64
#define DIN  128
#define D1   256

// ---------------- device scratch ----------------
__device__ __half g_xs[NN * D1];        // fp16 messages (xs = X @ Wsrc)
__device__ float  g_acc[NN * D1];       // layer-1 skip accumulator (float)
__device__ __half g_hh[NN * D1];        // hidden after LN+ReLU (fp16)
__device__ float  g_asad[NN * 8];       // per node: a_s[0..3], a_d[0..3]
__device__ float  g_vcat[D1 * 8];
__device__ int    g_deg[NN];
__device__ int    g_rowptr[NN + 1];
__device__ int    g_cursor[NN];
__device__ int    g_csrc[EE];           // CSR position -> src node

// ---------------- CSR build ----------------
__global__ void k_count(const int* __restrict__ dst) {
    int t = blockIdx.x * blockDim.x + threadIdx.x;
    if (t < EE) atomicAdd(&g_deg[dst[t]], 1);
}

__global__ void k_scan() {
    __shared__ int sums[1024];
    int t = threadIdx.x;
    const int CH = (NN + 1023) / 1024;
    int base = t * CH;
    int s = 0;
    for (int i = 0; i < CH; i++) {
        int idx = base + i;
        if (idx < NN) s += g_deg[idx];
    }
    int my = s;
    sums[t] = s;
    __syncthreads();
    for (int d = 1; d < 1024; d <<= 1) {
        int v = (t >= d) ? sums[t - d] : 0;
        __syncthreads();
        sums[t] += v;
        __syncthreads();
    }
    if (t == 1023) g_rowptr[NN] = sums[1023];
    int off = sums[t] - my;
    for (int i = 0; i < CH; i++) {
        int idx = base + i;
        if (idx < NN) {
            g_rowptr[idx] = off;
            g_cursor[idx] = off;
            off += g_deg[idx];
        }
    }
}

__global__ void k_fill(const int* __restrict__ dst, const int* __restrict__ src) {
    int t = blockIdx.x * blockDim.x + threadIdx.x;
    if (t < EE) {
        int p = atomicAdd(&g_cursor[dst[t]], 1);
        g_csrc[p] = src[t];
    }
}

// ---------------- fold att vectors ----------------
__global__ void k_vcat(const float* __restrict__ Wsrc, const float* __restrict__ Wdst,
                       const float* __restrict__ atts, const float* __restrict__ attd, int K) {
    int t = blockIdx.x * blockDim.x + threadIdx.x;
    if (t >= K * 8) return;
    int k = t >> 3, j = t & 7;
    const float* W   = (j < 4) ? Wsrc : Wdst;
    const float* att = (j < 4) ? atts : attd;
    int h = j & 3;
    float s = 0.f;
    for (int c = 0; c < CC; c++) s = fmaf(W[k * D1 + h * CC + c], att[h * CC + c], s);
    g_vcat[t] = s;
}

// ---------------- fp16 MMA helper ----------------
__device__ __forceinline__ void mma_f16(float* d, const uint32_t* a, const uint32_t* b) {
    asm volatile(
        "mma.sync.aligned.m16n8k16.row.col.f32.f16.f16.f32 "
        "{%0,%1,%2,%3}, {%4,%5,%6,%7}, {%8,%9}, {%0,%1,%2,%3};"
        : "+f"(d[0]), "+f"(d[1]), "+f"(d[2]), "+f"(d[3])
        : "r"(a[0]), "r"(a[1]), "r"(a[2]), "r"(a[3]), "r"(b[0]), "r"(b[1]));
}

__device__ __forceinline__ uint32_t pack_half2(float x, float y) {
    __half2 t = __floats2half2_rn(x, y);
    return *(uint32_t*)&t;
}

// ---------------- fused dual GEMM, fp16 inputs, f32 accum (BM=128,BN=64,BK=32) ----------------
template <int K, typename TA>
__global__ void __launch_bounds__(256)
k_dualgemm(const TA* __restrict__ X,
           const float* __restrict__ W1, const float* __restrict__ W2,
           const float* __restrict__ b2a, const float* __restrict__ b2b,
           __half* __restrict__ Y1, float* __restrict__ Y2) {
    __shared__ __align__(16) uint32_t As[2][128][20];
    __shared__ __align__(16) uint32_t Bs1[2][16][72];
    __shared__ __align__(16) uint32_t Bs2[2][16][72];

    const int tid = threadIdx.x;
    const int bm = blockIdx.x * 128, bn = blockIdx.y * 64;
    const int lane = tid & 31, wid = tid >> 5;
    const int wm = wid >> 1, wn = wid & 1;
    const int gid = lane >> 2, tig = lane & 3;

    const int kp = tid >> 4, nq = tid & 15;

    float4 raf[4];
    uint4  rah[2];
    float4 rb1a, rb1b, rb2a, rb2b;

    float acc[2][2][4][4];
#pragma unroll
    for (int m = 0; m < 2; m++)
#pragma unroll
        for (int i = 0; i < 2; i++)
#pragma unroll
            for (int j = 0; j < 4; j++)
#pragma unroll
                for (int q = 0; q < 4; q++) acc[m][i][j][q] = 0.f;

    const int KT = K / 32;

    auto load_tile = [&](int k0) {
        if constexpr (sizeof(TA) == 4) {
#pragma unroll
            for (int i = 0; i < 4; i++) {
                int f = tid + i * 256;
                int row = f >> 3, seg = f & 7;
                int gr = bm + row;
                float4 v = make_float4(0.f, 0.f, 0.f, 0.f);
                if (gr < NN) v = *(const float4*)((const float*)X + (size_t)gr * K + k0 + seg * 4);
                raf[i] = v;
            }
        } else {
#pragma unroll
            for (int i = 0; i < 2; i++) {
                int f = tid + i * 256;
                int row = f >> 2, sq = f & 3;
                int gr = bm + row;
                uint4 v = make_uint4(0u, 0u, 0u, 0u);
                if (gr < NN) v = *(const uint4*)((const __half*)X + (size_t)gr * K + k0 + sq * 8);
                rah[i] = v;
            }
        }
        rb1a = *(const float4*)(W1 + (size_t)(k0 + 2 * kp) * D1 + bn + nq * 4);
        rb1b = *(const float4*)(W1 + (size_t)(k0 + 2 * kp + 1) * D1 + bn + nq * 4);
        rb2a = *(const float4*)(W2 + (size_t)(k0 + 2 * kp) * D1 + bn + nq * 4);
        rb2b = *(const float4*)(W2 + (size_t)(k0 + 2 * kp + 1) * D1 + bn + nq * 4);
    };

    auto store_tile = [&](int st) {
        if constexpr (sizeof(TA) == 4) {
#pragma unroll
            for (int i = 0; i < 4; i++) {
                int f = tid + i * 256;
                int row = f >> 3, seg = f & 7;
                uint2 h;
                h.x = pack_half2(raf[i].x, raf[i].y);
                h.y = pack_half2(raf[i].z, raf[i].w);
                *(uint2*)&As[st][row][seg * 2] = h;
            }
        } else {
#pragma unroll
            for (int i = 0; i < 2; i++) {
                int f = tid + i * 256;
                int row = f >> 2, sq = f & 3;
                *(uint4*)&As[st][row][sq * 4] = rah[i];
            }
        }
        uint4 w;
        w.x = pack_half2(rb1a.x, rb1b.x);
        w.y = pack_half2(rb1a.y, rb1b.y);
        w.z = pack_half2(rb1a.z, rb1b.z);
        w.w = pack_half2(rb1a.w, rb1b.w);
        *(uint4*)&Bs1[st][kp][nq * 4] = w;
        w.x = pack_half2(rb2a.x, rb2b.x);
        w.y = pack_half2(rb2a.y, rb2b.y);
        w.z = pack_half2(rb2a.z, rb2b.z);
        w.w = pack_half2(rb2a.w, rb2b.w);
        *(uint4*)&Bs2[st][kp][nq * 4] = w;
    };

    load_tile(0);
    store_tile(0);
    __syncthreads();

    for (int kt = 0; kt < KT; kt++) {
        const int cur = kt & 1;
        const int nxt = cur ^ 1;
        if (kt + 1 < KT) load_tile((kt + 1) * 32);

#pragma unroll
        for (int ks = 0; ks < 2; ks++) {
            uint32_t a[2][4], bf1[4][2], bf2[4][2];
#pragma unroll
            for (int mt = 0; mt < 2; mt++) {
                int mr = wm * 32 + mt * 16 + gid;
                int kw = ks * 8 + tig;
                a[mt][0] = As[cur][mr][kw];
                a[mt][1] = As[cur][mr + 8][kw];
                a[mt][2] = As[cur][mr][kw + 4];
                a[mt][3] = As[cur][mr + 8][kw + 4];
            }
#pragma unroll
            for (int nt = 0; nt < 4; nt++) {
                int nc = wn * 32 + nt * 8 + gid;
                int kq = ks * 8 + tig;
                bf1[nt][0] = Bs1[cur][kq][nc];
                bf1[nt][1] = Bs1[cur][kq + 4][nc];
                bf2[nt][0] = Bs2[cur][kq][nc];
                bf2[nt][1] = Bs2[cur][kq + 4][nc];
            }
#pragma unroll
            for (int mt = 0; mt < 2; mt++)
#pragma unroll
                for (int nt = 0; nt < 4; nt++) {
                    mma_f16(acc[0][mt][nt], a[mt], bf1[nt]);
                    mma_f16(acc[1][mt][nt], a[mt], bf2[nt]);
                }
        }

        if (kt + 1 < KT) store_tile(nxt);
        __syncthreads();
    }

#pragma unroll
    for (int mt = 0; mt < 2; mt++) {
#pragma unroll
        for (int nt = 0; nt < 4; nt++) {
            int r0 = bm + wm * 32 + mt * 16 + gid;
            int c0 = bn + wn * 32 + nt * 8 + tig * 2;
            float bb0 = b2a[c0] + b2b[c0];
            float bb1 = b2a[c0 + 1] + b2b[c0 + 1];
            if (r0 < NN) {
                __half2 h = __floats2half2_rn(acc[0][mt][nt][0], acc[0][mt][nt][1]);
                *(__half2*)(Y1 + (size_t)r0 * D1 + c0) = h;
                *(float2*)(Y2 + (size_t)r0 * D1 + c0) =
                    make_float2(acc[1][mt][nt][0] + bb0, acc[1][mt][nt][1] + bb1);
            }
            if (r0 + 8 < NN) {
                __half2 h = __floats2half2_rn(acc[0][mt][nt][2], acc[0][mt][nt][3]);
                *(__half2*)(Y1 + (size_t)(r0 + 8) * D1 + c0) = h;
                *(float2*)(Y2 + (size_t)(r0 + 8) * D1 + c0) =
                    make_float2(acc[1][mt][nt][2] + bb0, acc[1][mt][nt][3] + bb1);
            }
        }
    }
}

// ---------------- a_s/a_d: warp per node ----------------
template <int K, typename TA>
__global__ void k_asad(const TA* __restrict__ X) {
    int w = (blockIdx.x * blockDim.x + threadIdx.x) >> 5;
    int l = threadIdx.x & 31;
    if (w >= NN) return;
    const TA* xr = X + (size_t)w * K;
    float s[8] = {0.f, 0.f, 0.f, 0.f, 0.f, 0.f, 0.f, 0.f};
#pragma unroll
    for (int q = 0; q < K / 32; q++) {
        int k = l + 32 * q;
        float xv;
        if constexpr (sizeof(TA) == 4) xv = (float)xr[k];
        else                           xv = __half2float(xr[k]);
        float4 v0 = *(const float4*)&g_vcat[k * 8];
        float4 v1 = *(const float4*)&g_vcat[k * 8 + 4];
        s[0] = fmaf(xv, v0.x, s[0]); s[1] = fmaf(xv, v0.y, s[1]);
        s[2] = fmaf(xv, v0.z, s[2]); s[3] = fmaf(xv, v0.w, s[3]);
        s[4] = fmaf(xv, v1.x, s[4]); s[5] = fmaf(xv, v1.y, s[5]);
        s[6] = fmaf(xv, v1.z, s[6]); s[7] = fmaf(xv, v1.w, s[7]);
    }
#pragma unroll
    for (int j = 0; j < 8; j++) {
#pragma unroll
        for (int d = 16; d > 0; d >>= 1) s[j] += __shfl_xor_sync(0xFFFFFFFFu, s[j], d);
    }
    if (l < 8) g_asad[w * 8 + l] = s[l];
}

// ---------------- aggregation core with inline softmax ----------------
// Softmax is shift invariant; scores are O(1) so exp cannot overflow.
__device__ __forceinline__ void agg_row(int w, int l, const __half* __restrict__ xs,
                                        float* acc, float& inv) {
    int rs = g_rowptr[w], re = g_rowptr[w + 1];
    int head = l >> 3;
    float ad = g_asad[w * 8 + 4 + head];
    float den = 0.f;
    int p = rs;
    for (; p + 1 < re; p += 2) {
        int s0 = g_csrc[p], s1 = g_csrc[p + 1];
        float e0 = g_asad[s0 * 8 + head] + ad;
        float e1 = g_asad[s1 * 8 + head] + ad;
        e0 = (e0 > 0.f) ? e0 : 0.2f * e0;
        e1 = (e1 > 0.f) ? e1 : 0.2f * e1;
        float a0 = __expf(e0);
        float a1 = __expf(e1);
        den += a0 + a1;
        uint4 v0 = *(const uint4*)(xs + (size_t)s0 * D1 + l * 8);
        uint4 v1 = *(const uint4*)(xs + (size_t)s1 * D1 + l * 8);
        const __half2* h0 = (const __half2*)&v0;
        const __half2* h1 = (const __half2*)&v1;
#pragma unroll
        for (int j = 0; j < 4; j++) {
            float2 f0 = __half22float2(h0[j]);
            float2 f1 = __half22float2(h1[j]);
            acc[2 * j]     = fmaf(a0, f0.x, acc[2 * j]);
            acc[2 * j + 1] = fmaf(a0, f0.y, acc[2 * j + 1]);
            acc[2 * j]     = fmaf(a1, f1.x, acc[2 * j]);
            acc[2 * j + 1] = fmaf(a1, f1.y, acc[2 * j + 1]);
        }
    }
    if (p < re) {
        int s0 = g_csrc[p];
        float e0 = g_asad[s0 * 8 + head] + ad;
        e0 = (e0 > 0.f) ? e0 : 0.2f * e0;
        float a0 = __expf(e0);
        den += a0;
        uint4 v0 = *(const uint4*)(xs + (size_t)s0 * D1 + l * 8);
        const __half2* h0 = (const __half2*)&v0;
#pragma unroll
        for (int j = 0; j < 4; j++) {
            float2 f0 = __half22float2(h0[j]);
            acc[2 * j]     = fmaf(a0, f0.x, acc[2 * j]);
            acc[2 * j + 1] = fmaf(a0, f0.y, acc[2 * j + 1]);
        }
    }
    inv = 1.f / (den + 1e-16f);
}

// ---------------- layer-1: aggregate + skip + LayerNorm + ReLU -> half h ----------------
__global__ void k_agg_ln(const __half* __restrict__ xs, const float* __restrict__ skip,
                         __half* __restrict__ hout,
                         const float* __restrict__ gamma, const float* __restrict__ beta) {
    int w = (blockIdx.x * blockDim.x + threadIdx.x) >> 5;
    int l = threadIdx.x & 31;
    if (w >= NN) return;
    float m[8] = {0.f, 0.f, 0.f, 0.f, 0.f, 0.f, 0.f, 0.f};
    float inv;
    agg_row(w, l, xs, m, inv);

    const float* sk = skip + (size_t)w * D1 + l * 8;
    float4 s0 = *(const float4*)(sk);
    float4 s1 = *(const float4*)(sk + 4);
    float v[8] = {s0.x + m[0] * inv, s0.y + m[1] * inv, s0.z + m[2] * inv, s0.w + m[3] * inv,
                  s1.x + m[4] * inv, s1.y + m[5] * inv, s1.z + m[6] * inv, s1.w + m[7] * inv};
    float sm = 0.f, sq = 0.f;
#pragma unroll
    for (int k = 0; k < 8; k++) { sm += v[k]; sq += v[k] * v[k]; }
#pragma unroll
    for (int d = 16; d > 0; d >>= 1) {
        sm += __shfl_xor_sync(0xFFFFFFFFu, sm, d);
        sq += __shfl_xor_sync(0xFFFFFFFFu, sq, d);
    }
    float mean = sm * (1.f / D1);
    float var = sq * (1.f / D1) - mean * mean;
    float rstd = rsqrtf(var + 1e-5f);
    const float* gp = gamma + l * 8;
    const float* bp = beta + l * 8;
    float4 g0 = *(const float4*)(gp);
    float4 g1 = *(const float4*)(gp + 4);
    float4 be0 = *(const float4*)(bp);
    float4 be1 = *(const float4*)(bp + 4);
    float r[8];
    r[0] = fmaxf((v[0] - mean) * rstd * g0.x + be0.x, 0.f);
    r[1] = fmaxf((v[1] - mean) * rstd * g0.y + be0.y, 0.f);
    r[2] = fmaxf((v[2] - mean) * rstd * g0.z + be0.z, 0.f);
    r[3] = fmaxf((v[3] - mean) * rstd * g0.w + be0.w, 0.f);
    r[4] = fmaxf((v[4] - mean) * rstd * g1.x + be1.x, 0.f);
    r[5] = fmaxf((v[5] - mean) * rstd * g1.y + be1.y, 0.f);
    r[6] = fmaxf((v[6] - mean) * rstd * g1.z + be1.z, 0.f);
    r[7] = fmaxf((v[7] - mean) * rstd * g1.w + be1.w, 0.f);
    uint4 hv;
    hv.x = pack_half2(r[0], r[1]);
    hv.y = pack_half2(r[2], r[3]);
    hv.z = pack_half2(r[4], r[5]);
    hv.w = pack_half2(r[6], r[7]);
    *(uint4*)(hout + (size_t)w * D1 + l * 8) = hv;
}

// ---------------- layer-2: aggregate into out ----------------
__global__ void k_agg2(const __half* __restrict__ xs, float* __restrict__ out) {
    int w = (blockIdx.x * blockDim.x + threadIdx.x) >> 5;
    int l = threadIdx.x & 31;
    if (w >= NN) return;
    int rs = g_rowptr[w], re = g_rowptr[w + 1];
    if (rs == re) return;
    float m[8] = {0.f, 0.f, 0.f, 0.f, 0.f, 0.f, 0.f, 0.f};
    float inv;
    agg_row(w, l, xs, m, inv);
    float* o = out + (size_t)w * D1 + l * 8;
    float4 t0 = *(const float4*)(o);
    float4 t1 = *(const float4*)(o + 4);
    t0.x = fmaf(m[0], inv, t0.x); t0.y = fmaf(m[1], inv, t0.y);
    t0.z = fmaf(m[2], inv, t0.z); t0.w = fmaf(m[3], inv, t0.w);
    t1.x = fmaf(m[4], inv, t1.x); t1.y = fmaf(m[5], inv, t1.y);
    t1.z = fmaf(m[6], inv, t1.z); t1.w = fmaf(m[7], inv, t1.w);
    *(float4*)(o) = t0;
    *(float4*)(o + 4) = t1;
}

// ---------------- host launch ----------------
extern "C" void kernel_launch(void* const* d_in, const int* in_sizes, int n_in,
                              void* d_out, int out_size) {
    const float* x     = (const float*)d_in[0];
    const int*   ei    = (const int*)d_in[1];
    const float* Wsrc1 = (const float*)d_in[2];
    const float* Wdst1 = (const float*)d_in[3];
    const float* atts1 = (const float*)d_in[4];
    const float* attd1 = (const float*)d_in[5];
    const float* b1    = (const float*)d_in[6];
    const float* Wlin1 = (const float*)d_in[7];
    const float* blin1 = (const float*)d_in[8];
    const float* gamma = (const float*)d_in[9];
    const float* beta  = (const float*)d_in[10];
    const float* Wsrc2 = (const float*)d_in[11];
    const float* Wdst2 = (const float*)d_in[12];
    const float* atts2 = (const float*)d_in[13];
    const float* attd2 = (const float*)d_in[14];
    const float* b2    = (const float*)d_in[15];
    const float* Wlin2 = (const float*)d_in[16];
    const float* blin2 = (const float*)d_in[17];
    float* out = (float*)d_out;

    const int* src = ei;
    const int* dst = ei + EE;

    __half *xs_p, *hh_p;
    float* acc_p;
    int* deg_p;
    cudaGetSymbolAddress((void**)&xs_p, g_xs);
    cudaGetSymbolAddress((void**)&acc_p, g_acc);
    cudaGetSymbolAddress((void**)&hh_p, g_hh);
    cudaGetSymbolAddress((void**)&deg_p, g_deg);

    // CSR (graph identical across layers)
    cudaMemsetAsync(deg_p, 0, NN * sizeof(int), 0);
    k_count<<<(EE + 255) / 256, 256>>>(dst);
    k_scan<<<1, 1024>>>();
    k_fill<<<(EE + 255) / 256, 256>>>(dst, src);

    dim3 gg((NN + 127) / 128, D1 / 64);

    // ---- layer 1 (K = 128, A fp32) ----
    k_vcat<<<(DIN * 8 + 255) / 256, 256>>>(Wsrc1, Wdst1, atts1, attd1, DIN);
    k_dualgemm<DIN, float><<<gg, 256>>>(x, Wsrc1, Wlin1, blin1, b1, xs_p, acc_p);
    k_asad<DIN, float><<<(NN * 32 + 255) / 256, 256>>>(x);
    k_agg_ln<<<(NN + 7) / 8, 256>>>(xs_p, acc_p, hh_p, gamma, beta);

    // ---- layer 2 (K = 256, A fp16) ----
    k_vcat<<<(D1 * 8 + 255) / 256, 256>>>(Wsrc2, Wdst2, atts2, attd2, D1);
    k_dualgemm<D1, __half><<<gg, 256>>>(hh_p, Wsrc2, Wlin2, blin2, b2, xs_p, out);
    k_asad<D1, __half><<<(NN * 32 + 255) / 256, 256>>>(hh_p);
    k_agg2<<<(NN + 7) / 8, 256>>>(xs_p, out);
}